// round 9
// baseline (speedup 1.0000x reference)
#include <cuda_runtime.h>
#include <cstddef>

// ---------------------------------------------------------------------------
// AttentionBlock: GroupNorm(32) -> QKV (1x1 conv) -> softmax(QK^T/sqrt(C)) V
//                 -> proj + residual.   B=2, H=W=64 (N=4096), C=512, fp32.
// ---------------------------------------------------------------------------

typedef unsigned long long u64;

#define BM 128
#define BN 128
#define BK 16

// Scratch (allocation-free: __device__ globals)
__device__ float g_xn [8192 * 512];
__device__ float g_q  [8192 * 512];
__device__ float g_k  [8192 * 512];
__device__ float g_v  [8192 * 512];
__device__ float g_o  [8192 * 512];
__device__ float g_attn[(size_t)2 * 4096 * 4096];
__device__ float g_mean[64];
__device__ float g_rstd[64];

// ---------------------------------------------------------------------------
// GroupNorm statistics: one block per (batch, group). 4096 pixels x 16 chans.
// ---------------------------------------------------------------------------
__global__ void gn_stats(const float* __restrict__ x) {
    int bg = blockIdx.x;              // 0..63
    int b  = bg >> 5;
    int g  = bg & 31;
    const float* base = x + (size_t)b * 4096 * 512 + g * 16;

    float s = 0.f, ss = 0.f;
    for (int i = threadIdx.x; i < 65536; i += 256) {
        int p = i >> 4, c = i & 15;
        float v = base[(size_t)p * 512 + c];
        s += v; ss += v * v;
    }
    __shared__ float sh1[256], sh2[256];
    sh1[threadIdx.x] = s; sh2[threadIdx.x] = ss;
    __syncthreads();
    for (int st = 128; st > 0; st >>= 1) {
        if (threadIdx.x < st) {
            sh1[threadIdx.x] += sh1[threadIdx.x + st];
            sh2[threadIdx.x] += sh2[threadIdx.x + st];
        }
        __syncthreads();
    }
    if (threadIdx.x == 0) {
        float m   = sh1[0] * (1.f / 65536.f);
        float var = sh2[0] * (1.f / 65536.f) - m * m;
        g_mean[bg] = m;
        g_rstd[bg] = rsqrtf(var + 1e-5f);
    }
}

// ---------------------------------------------------------------------------
// Apply GroupNorm: xn = (x - mean) * rstd * gamma + beta   (float4 per thread)
// ---------------------------------------------------------------------------
__global__ void gn_apply(const float* __restrict__ x,
                         const float* __restrict__ gamma,
                         const float* __restrict__ beta) {
    size_t i4 = (size_t)blockIdx.x * blockDim.x + threadIdx.x;
    size_t e  = i4 * 4;                       // 4,194,304 elements total
    int c = (int)(e & 511);
    int b = (int)(e >> 21);                   // 4096*512 = 2^21
    int bg = b * 32 + (c >> 4);
    float m = g_mean[bg], r = g_rstd[bg];
    float4 xv = *(const float4*)(x + e);
    float4 o;
    o.x = (xv.x - m) * r * gamma[c + 0] + beta[c + 0];
    o.y = (xv.y - m) * r * gamma[c + 1] + beta[c + 1];
    o.z = (xv.z - m) * r * gamma[c + 2] + beta[c + 2];
    o.w = (xv.w - m) * r * gamma[c + 3] + beta[c + 3];
    *(float4*)(g_xn + e) = o;
}

// ---------------------------------------------------------------------------
// Tiled GEMM, fp32 with packed f32x2 FMA (FFMA2) inner loop.
//   C = scale * (A @ B or A @ B^T) + bias + residual
//   A: [M,K] row-major.  B: NN -> [K,N] row-major; NT -> [N,K] row-major.
//   Batched via blockIdx.z with element strides sA/sB/sC. residual has C layout
//   (only used with z=1 grids here).
// Tile: 128x128x16, 256 threads, 8x8 per thread.
// ---------------------------------------------------------------------------
template <bool BT>
__global__ void __launch_bounds__(256, 2)
gemm_f32x2(const float* __restrict__ A, const float* __restrict__ B,
           float* __restrict__ C, const float* __restrict__ bias,
           const float* __restrict__ residual,
           int M, int N, int K, float scale,
           size_t sA, size_t sB, size_t sC) {
    A += (size_t)blockIdx.z * sA;
    B += (size_t)blockIdx.z * sB;
    C += (size_t)blockIdx.z * sC;

    __shared__ __align__(16) float As[BK][BM];
    __shared__ __align__(16) float Bs[BK][BN];

    const int tid  = threadIdx.x;
    const int row0 = blockIdx.y * BM;
    const int col0 = blockIdx.x * BN;

    // A / (NT) B global-load mapping: coalesced 64B per row.
    const int lr = tid >> 2;              // row within tile (0..63), +64 second
    const int lk = (tid & 3) * 4;         // k quad
    // NN B load mapping: full 512B rows.
    const int bkr = tid >> 5;             // k row (0..7), +8 second
    const int bn4 = (tid & 31) * 4;       // n quad

    const int tm = (tid >> 4) * 8;
    const int tn = (tid & 15) * 8;

    u64 acc[8][4];
#pragma unroll
    for (int i = 0; i < 8; i++)
#pragma unroll
        for (int j = 0; j < 4; j++) acc[i][j] = 0ull;

    for (int kt = 0; kt < K; kt += BK) {
        // --- load A tile (transpose into As[k][m]) ---
        {
            float4 v0 = *(const float4*)(A + (size_t)(row0 + lr) * K + kt + lk);
            float4 v1 = *(const float4*)(A + (size_t)(row0 + lr + 64) * K + kt + lk);
            As[lk + 0][lr] = v0.x; As[lk + 1][lr] = v0.y;
            As[lk + 2][lr] = v0.z; As[lk + 3][lr] = v0.w;
            As[lk + 0][lr + 64] = v1.x; As[lk + 1][lr + 64] = v1.y;
            As[lk + 2][lr + 64] = v1.z; As[lk + 3][lr + 64] = v1.w;
        }
        // --- load B tile into Bs[k][n] ---
        if (BT) {
            float4 v0 = *(const float4*)(B + (size_t)(col0 + lr) * K + kt + lk);
            float4 v1 = *(const float4*)(B + (size_t)(col0 + lr + 64) * K + kt + lk);
            Bs[lk + 0][lr] = v0.x; Bs[lk + 1][lr] = v0.y;
            Bs[lk + 2][lr] = v0.z; Bs[lk + 3][lr] = v0.w;
            Bs[lk + 0][lr + 64] = v1.x; Bs[lk + 1][lr + 64] = v1.y;
            Bs[lk + 2][lr + 64] = v1.z; Bs[lk + 3][lr + 64] = v1.w;
        } else {
            *(float4*)&Bs[bkr][bn4] =
                *(const float4*)(B + (size_t)(kt + bkr) * N + col0 + bn4);
            *(float4*)&Bs[bkr + 8][bn4] =
                *(const float4*)(B + (size_t)(kt + bkr + 8) * N + col0 + bn4);
        }
        __syncthreads();

#pragma unroll
        for (int k = 0; k < BK; k++) {
            float a[8];
            u64 bb[4];
            *(float4*)&a[0] = *(const float4*)&As[k][tm];
            *(float4*)&a[4] = *(const float4*)&As[k][tm + 4];
            ulonglong2 t0 = *(const ulonglong2*)&Bs[k][tn];
            ulonglong2 t1 = *(const ulonglong2*)&Bs[k][tn + 4];
            bb[0] = t0.x; bb[1] = t0.y; bb[2] = t1.x; bb[3] = t1.y;
#pragma unroll
            for (int i = 0; i < 8; i++) {
                unsigned ai = __float_as_uint(a[i]);
                u64 ad;
                asm("mov.b64 %0, {%1, %1};" : "=l"(ad) : "r"(ai));
#pragma unroll
                for (int j = 0; j < 4; j++) {
                    asm("fma.rn.f32x2 %0, %1, %2, %3;"
                        : "=l"(acc[i][j])
                        : "l"(ad), "l"(bb[j]), "l"(acc[i][j]));
                }
            }
        }
        __syncthreads();
    }

    // --- epilogue ---
#pragma unroll
    for (int i = 0; i < 8; i++) {
        size_t crow = (size_t)(row0 + tm + i) * N + col0 + tn;
        float out[8];
#pragma unroll
        for (int j = 0; j < 4; j++) {
            unsigned lo = (unsigned)acc[i][j];
            unsigned hi = (unsigned)(acc[i][j] >> 32);
            out[2 * j]     = __uint_as_float(lo) * scale;
            out[2 * j + 1] = __uint_as_float(hi) * scale;
        }
        if (bias) {
#pragma unroll
            for (int j = 0; j < 8; j++) out[j] += bias[col0 + tn + j];
        }
        if (residual) {
            float4 r0 = *(const float4*)(residual + crow);
            float4 r1 = *(const float4*)(residual + crow + 4);
            out[0] += r0.x; out[1] += r0.y; out[2] += r0.z; out[3] += r0.w;
            out[4] += r1.x; out[5] += r1.y; out[6] += r1.z; out[7] += r1.w;
        }
        *(float4*)(C + crow)     = make_float4(out[0], out[1], out[2], out[3]);
        *(float4*)(C + crow + 4) = make_float4(out[4], out[5], out[6], out[7]);
    }
}

// ---------------------------------------------------------------------------
// Row softmax, row length 4096, one block (256 threads) per row, in-place.
// ---------------------------------------------------------------------------
__global__ void softmax4096(float* __restrict__ S) {
    float* p = S + (size_t)blockIdx.x * 4096;
    const int t = threadIdx.x;
    __shared__ float sh[8];

    float v[16];
    float mx = -1e30f;
#pragma unroll
    for (int i = 0; i < 16; i++) {
        v[i] = p[t + i * 256];
        mx = fmaxf(mx, v[i]);
    }
#pragma unroll
    for (int off = 16; off > 0; off >>= 1)
        mx = fmaxf(mx, __shfl_xor_sync(0xffffffffu, mx, off));
    if ((t & 31) == 0) sh[t >> 5] = mx;
    __syncthreads();
    {
        float m = sh[t & 7];
#pragma unroll
        for (int off = 4; off > 0; off >>= 1)
            m = fmaxf(m, __shfl_xor_sync(0xffffffffu, m, off));
        mx = m;
    }
    __syncthreads();

    float s = 0.f;
#pragma unroll
    for (int i = 0; i < 16; i++) {
        v[i] = __expf(v[i] - mx);
        s += v[i];
    }
#pragma unroll
    for (int off = 16; off > 0; off >>= 1)
        s += __shfl_xor_sync(0xffffffffu, s, off);
    if ((t & 31) == 0) sh[t >> 5] = s;
    __syncthreads();
    {
        float m = sh[t & 7];
#pragma unroll
        for (int off = 4; off > 0; off >>= 1)
            m += __shfl_xor_sync(0xffffffffu, m, off);
        s = m;
    }

    float inv = 1.f / s;
#pragma unroll
    for (int i = 0; i < 16; i++) p[t + i * 256] = v[i] * inv;
}

// ---------------------------------------------------------------------------
// Launch
// ---------------------------------------------------------------------------
extern "C" void kernel_launch(void* const* d_in, const int* in_sizes, int n_in,
                              void* d_out, int out_size) {
    (void)in_sizes; (void)n_in; (void)out_size;

    const float* x     = (const float*)d_in[0];
    const float* gamma = (const float*)d_in[1];
    const float* beta  = (const float*)d_in[2];
    const float* wq    = (const float*)d_in[3];
    const float* bq    = (const float*)d_in[4];
    const float* wk    = (const float*)d_in[5];
    const float* bk    = (const float*)d_in[6];
    const float* wv    = (const float*)d_in[7];
    const float* bv    = (const float*)d_in[8];
    const float* wp    = (const float*)d_in[9];
    const float* bp    = (const float*)d_in[10];
    float* out = (float*)d_out;

    float *xn, *q, *k, *v, *o, *attn;
    cudaGetSymbolAddress((void**)&xn,   g_xn);
    cudaGetSymbolAddress((void**)&q,    g_q);
    cudaGetSymbolAddress((void**)&k,    g_k);
    cudaGetSymbolAddress((void**)&v,    g_v);
    cudaGetSymbolAddress((void**)&o,    g_o);
    cudaGetSymbolAddress((void**)&attn, g_attn);

    const float SCALE = 0.04419417382415922f;  // 1/sqrt(512)
    const size_t sQ = (size_t)4096 * 512;      // per-batch q/k/v/o stride
    const size_t sS = (size_t)4096 * 4096;     // per-batch attn stride

    // GroupNorm
    gn_stats<<<64, 256>>>(x);
    gn_apply<<<4096, 256>>>(x, gamma, beta);

    // QKV projections: [8192,512] @ [512,512]
    dim3 gQKV(512 / BN, 8192 / BM, 1);
    gemm_f32x2<false><<<gQKV, 256>>>(xn, wq, q, bq, nullptr, 8192, 512, 512, 1.f, 0, 0, 0);
    gemm_f32x2<false><<<gQKV, 256>>>(xn, wk, k, bk, nullptr, 8192, 512, 512, 1.f, 0, 0, 0);
    gemm_f32x2<false><<<gQKV, 256>>>(xn, wv, v, bv, nullptr, 8192, 512, 512, 1.f, 0, 0, 0);

    // S = scale * Q @ K^T  (per batch)
    dim3 gS(4096 / BN, 4096 / BM, 2);
    gemm_f32x2<true><<<gS, 256>>>(q, k, attn, nullptr, nullptr, 4096, 4096, 512, SCALE, sQ, sQ, sS);

    // softmax rows
    softmax4096<<<8192, 256>>>(attn);

    // O = P @ V  (per batch)
    dim3 gPV(512 / BN, 4096 / BM, 2);
    gemm_f32x2<false><<<gPV, 256>>>(attn, v, o, nullptr, nullptr, 4096, 512, 4096, 1.f, sS, sQ, sQ);

    // out = O @ wp + bp + x
    dim3 gP(512 / BN, 8192 / BM, 1);
    gemm_f32x2<false><<<gP, 256>>>(o, wp, out, bp, x, 8192, 512, 512, 1.f, 0, 0, 0);
}

// round 11
// speedup vs baseline: 3.4554x; 3.4554x over previous
#include <cuda_runtime.h>
#include <cstdint>
#include <cstddef>

// ---------------------------------------------------------------------------
// AttentionBlock via mma.sync tf32 (HMMA path — tcgen05 PTX is rejected because
// the harness PTX target is plain sm_103, not sm_103a).
//   GroupNorm(32) -> QKV -> softmax(QK^T/sqrt(C)) V -> proj + residual
//   B=2, N_tok=4096, C=512, fp32 I/O.
// All GEMMs are NT: D[m,n] = sum_k A[m,k]*B[n,k]; weights / V pre-transposed.
// ---------------------------------------------------------------------------

typedef unsigned long long u64;

// ---------------- GEMM tile config ----------------
#define BM 128
#define BN 128
#define BK 32                       // fp32 elements per chunk (4 MMA k-steps of 8)
#define NST 3                       // cp.async pipeline stages
#define LDSTR 36                    // padded row stride in floats (32 -> 36)
#define A_FLOATS (BM * LDSTR)       // 4608 floats per A tile
#define STG_FLOATS (2 * A_FLOATS)   // 9216 floats per stage (A + B)
#define GEMM_SMEM (NST * STG_FLOATS * 4)   // 110592 bytes

// ---------------- scratch (allocation-free) ----------------
__device__ float g_xn  [8192 * 512];
__device__ float g_q   [8192 * 512];
__device__ float g_k   [8192 * 512];
__device__ float g_v   [8192 * 512];
__device__ float g_o   [8192 * 512];
__device__ float g_vt  [8192 * 512];                 // V^T per batch: [512,4096]
__device__ float g_wt  [4 * 512 * 512];              // wq^T, wk^T, wv^T, wp^T
__device__ float g_attn[(size_t)2 * 4096 * 4096];
__device__ float g_mean[64];
__device__ float g_rstd[64];

// ---------------- helpers ----------------
__device__ __forceinline__ uint32_t smem_u32(const void* p) {
    uint32_t a;
    asm("{ .reg .u64 t; cvta.to.shared.u64 t, %1; cvt.u32.u64 %0, t; }" : "=r"(a) : "l"(p));
    return a;
}
__device__ __forceinline__ void cpa16(uint32_t dst, const float* src) {
    asm volatile("cp.async.cg.shared.global [%0], [%1], 16;" :: "r"(dst), "l"(src));
}

// ---------------------------------------------------------------------------
// GroupNorm
// ---------------------------------------------------------------------------
__global__ void gn_stats(const float* __restrict__ x) {
    int bg = blockIdx.x, b = bg >> 5, g = bg & 31;
    const float* base = x + (size_t)b * 4096 * 512 + g * 16;
    float s = 0.f, ss = 0.f;
    for (int i = threadIdx.x; i < 65536; i += 256) {
        int p = i >> 4, c = i & 15;
        float v = base[(size_t)p * 512 + c];
        s += v; ss += v * v;
    }
    __shared__ float sh1[256], sh2[256];
    sh1[threadIdx.x] = s; sh2[threadIdx.x] = ss;
    __syncthreads();
    for (int st = 128; st > 0; st >>= 1) {
        if (threadIdx.x < st) {
            sh1[threadIdx.x] += sh1[threadIdx.x + st];
            sh2[threadIdx.x] += sh2[threadIdx.x + st];
        }
        __syncthreads();
    }
    if (threadIdx.x == 0) {
        float m = sh1[0] * (1.f / 65536.f);
        float var = sh2[0] * (1.f / 65536.f) - m * m;
        g_mean[bg] = m;
        g_rstd[bg] = rsqrtf(var + 1e-5f);
    }
}

__global__ void gn_apply(const float* __restrict__ x,
                         const float* __restrict__ gamma,
                         const float* __restrict__ beta) {
    size_t e = ((size_t)blockIdx.x * blockDim.x + threadIdx.x) * 4;
    int c = (int)(e & 511);
    int b = (int)(e >> 21);
    int bg = b * 32 + (c >> 4);
    float m = g_mean[bg], r = g_rstd[bg];
    float4 xv = *(const float4*)(x + e);
    float4 o;
    o.x = (xv.x - m) * r * gamma[c + 0] + beta[c + 0];
    o.y = (xv.y - m) * r * gamma[c + 1] + beta[c + 1];
    o.z = (xv.z - m) * r * gamma[c + 2] + beta[c + 2];
    o.w = (xv.w - m) * r * gamma[c + 3] + beta[c + 3];
    *(float4*)(g_xn + e) = o;
}

// ---------------------------------------------------------------------------
// Transpose: out[b][c][r] = in[b][r][c].  grid(C/32, R/32, batch), block(32,8)
// ---------------------------------------------------------------------------
__global__ void transpose_k(const float* __restrict__ in, float* __restrict__ out,
                            int R, int C, size_t sIn, size_t sOut) {
    in  += (size_t)blockIdx.z * sIn;
    out += (size_t)blockIdx.z * sOut;
    __shared__ float t[32][33];
    int c0 = blockIdx.x * 32, r0 = blockIdx.y * 32;
    int tx = threadIdx.x, ty = threadIdx.y;
#pragma unroll
    for (int i = 0; i < 32; i += 8)
        t[ty + i][tx] = in[(size_t)(r0 + ty + i) * C + c0 + tx];
    __syncthreads();
#pragma unroll
    for (int i = 0; i < 32; i += 8)
        out[(size_t)(c0 + ty + i) * R + r0 + tx] = t[tx][ty + i];
}

// ---------------------------------------------------------------------------
// tf32 mma.sync GEMM (NT): D = scale*(A @ B^T) + bias + residual
//   A [M,K] row-major, B [N,K] row-major, D [M,N] row-major.
//   CTA tile 128x128x32, 8 warps (2m x 4n), warp tile 64x32, mma m16n8k8.
//   grid(N/128, M/128, batch), 256 threads, 3-stage cp.async pipeline.
// ---------------------------------------------------------------------------
__global__ void __launch_bounds__(256, 2)
gemm_mma(const float* __restrict__ A, const float* __restrict__ B,
         float* __restrict__ C, const float* __restrict__ bias,
         const float* __restrict__ residual,
         int M, int N, int K, float scale,
         size_t sA, size_t sB, size_t sC) {
    extern __shared__ float smem[];
    const uint32_t saddr = smem_u32(smem);
    const int tid = threadIdx.x;
    const int wid = tid >> 5, lid = tid & 31;
    const int gid = lid >> 2, tig = lid & 3;     // quad row / thread-in-group
    const int wm  = wid >> 2, wn  = wid & 3;     // warp grid 2x4

    const int row0 = blockIdx.y * BM;
    const int col0 = blockIdx.x * BN;
    const float* Ab = A + (size_t)blockIdx.z * sA + (size_t)row0 * K;
    const float* Bb = B + (size_t)blockIdx.z * sB + (size_t)col0 * K;

    float acc[4][4][4];
#pragma unroll
    for (int i = 0; i < 4; i++)
#pragma unroll
        for (int j = 0; j < 4; j++)
#pragma unroll
            for (int r = 0; r < 4; r++) acc[i][j][r] = 0.f;

    const int nch = K / BK;

    auto load_stage = [&](int s, int kt) {
        uint32_t dA = saddr + (uint32_t)(s * STG_FLOATS) * 4u;
        uint32_t dB = dA + (uint32_t)A_FLOATS * 4u;
        const float* Ak = Ab + kt * BK;
        const float* Bk = Bb + kt * BK;
#pragma unroll
        for (int i = 0; i < 4; i++) {            // A: 128 rows x 8 x 16B
            int idx = tid + 256 * i;
            int r = idx >> 3, e = idx & 7;
            cpa16(dA + (uint32_t)(r * LDSTR + e * 4) * 4u, Ak + (size_t)r * K + e * 4);
        }
#pragma unroll
        for (int i = 0; i < 4; i++) {            // B: 128 rows x 8 x 16B
            int idx = tid + 256 * i;
            int r = idx >> 3, e = idx & 7;
            cpa16(dB + (uint32_t)(r * LDSTR + e * 4) * 4u, Bk + (size_t)r * K + e * 4);
        }
        asm volatile("cp.async.commit_group;" ::: "memory");
    };

    // prologue: stages 0,1 (nch >= 16 always here)
    load_stage(0, 0);
    load_stage(1, 1);

    for (int kt = 0; kt < nch; kt++) {
        int s = kt % NST;
        if (kt == nch - 1) asm volatile("cp.async.wait_group 0;" ::: "memory");
        else               asm volatile("cp.async.wait_group 1;" ::: "memory");
        __syncthreads();

        const uint32_t* As = (const uint32_t*)(smem + s * STG_FLOATS);
        const uint32_t* Bs = As + A_FLOATS;

#pragma unroll
        for (int ks = 0; ks < 4; ks++) {
            const int kb = ks * 8;
            uint32_t a[4][4], b[4][2];
#pragma unroll
            for (int mt = 0; mt < 4; mt++) {
                int r = wm * 64 + mt * 16 + gid;
                a[mt][0] = As[r * LDSTR + kb + tig];
                a[mt][1] = As[(r + 8) * LDSTR + kb + tig];
                a[mt][2] = As[r * LDSTR + kb + tig + 4];
                a[mt][3] = As[(r + 8) * LDSTR + kb + tig + 4];
            }
#pragma unroll
            for (int nt = 0; nt < 4; nt++) {
                int n = wn * 32 + nt * 8 + gid;
                b[nt][0] = Bs[n * LDSTR + kb + tig];
                b[nt][1] = Bs[n * LDSTR + kb + tig + 4];
            }
#pragma unroll
            for (int mt = 0; mt < 4; mt++)
#pragma unroll
                for (int nt = 0; nt < 4; nt++)
                    asm volatile(
                        "mma.sync.aligned.m16n8k8.row.col.f32.tf32.tf32.f32 "
                        "{%0,%1,%2,%3}, {%4,%5,%6,%7}, {%8,%9}, {%0,%1,%2,%3};"
                        : "+f"(acc[mt][nt][0]), "+f"(acc[mt][nt][1]),
                          "+f"(acc[mt][nt][2]), "+f"(acc[mt][nt][3])
                        : "r"(a[mt][0]), "r"(a[mt][1]), "r"(a[mt][2]), "r"(a[mt][3]),
                          "r"(b[nt][0]), "r"(b[nt][1]));
        }
        __syncthreads();
        if (kt + 2 < nch) load_stage((kt + 2) % NST, kt + 2);
    }

    // epilogue
    float* Cb = C + (size_t)blockIdx.z * sC;
    const float* Rb = residual ? residual + (size_t)blockIdx.z * sC : nullptr;
#pragma unroll
    for (int mt = 0; mt < 4; mt++) {
        int r = row0 + wm * 64 + mt * 16 + gid;
#pragma unroll
        for (int nt = 0; nt < 4; nt++) {
            int c = col0 + wn * 32 + nt * 8 + 2 * tig;
#pragma unroll
            for (int h = 0; h < 2; h++) {
                int rr = r + h * 8;
                float v0 = acc[mt][nt][2 * h + 0] * scale;
                float v1 = acc[mt][nt][2 * h + 1] * scale;
                if (bias) { v0 += bias[c]; v1 += bias[c + 1]; }
                if (Rb) {
                    float2 rv = *(const float2*)(Rb + (size_t)rr * N + c);
                    v0 += rv.x; v1 += rv.y;
                }
                *(float2*)(Cb + (size_t)rr * N + c) = make_float2(v0, v1);
            }
        }
    }
}

// ---------------------------------------------------------------------------
// Row softmax, length 4096, one 256-thread block per row, in-place.
// ---------------------------------------------------------------------------
__global__ void softmax4096(float* __restrict__ S) {
    float* p = S + (size_t)blockIdx.x * 4096;
    const int t = threadIdx.x;
    __shared__ float sh[8];

    float v[16];
    float mx = -1e30f;
#pragma unroll
    for (int i = 0; i < 16; i++) {
        v[i] = p[t + i * 256];
        mx = fmaxf(mx, v[i]);
    }
#pragma unroll
    for (int off = 16; off > 0; off >>= 1)
        mx = fmaxf(mx, __shfl_xor_sync(0xffffffffu, mx, off));
    if ((t & 31) == 0) sh[t >> 5] = mx;
    __syncthreads();
    {
        float m = sh[t & 7];
#pragma unroll
        for (int off = 4; off > 0; off >>= 1)
            m = fmaxf(m, __shfl_xor_sync(0xffffffffu, m, off));
        mx = m;
    }
    __syncthreads();

    float s = 0.f;
#pragma unroll
    for (int i = 0; i < 16; i++) {
        v[i] = __expf(v[i] - mx);
        s += v[i];
    }
#pragma unroll
    for (int off = 16; off > 0; off >>= 1)
        s += __shfl_xor_sync(0xffffffffu, s, off);
    if ((t & 31) == 0) sh[t >> 5] = s;
    __syncthreads();
    {
        float m = sh[t & 7];
#pragma unroll
        for (int off = 4; off > 0; off >>= 1)
            m += __shfl_xor_sync(0xffffffffu, m, off);
        s = m;
    }
    float inv = 1.f / s;
#pragma unroll
    for (int i = 0; i < 16; i++) p[t + i * 256] = v[i] * inv;
}

// ---------------------------------------------------------------------------
// Launch
// ---------------------------------------------------------------------------
extern "C" void kernel_launch(void* const* d_in, const int* in_sizes, int n_in,
                              void* d_out, int out_size) {
    (void)in_sizes; (void)n_in; (void)out_size;

    const float* x     = (const float*)d_in[0];
    const float* gamma = (const float*)d_in[1];
    const float* beta  = (const float*)d_in[2];
    const float* wq    = (const float*)d_in[3];
    const float* bq    = (const float*)d_in[4];
    const float* wk    = (const float*)d_in[5];
    const float* bk    = (const float*)d_in[6];
    const float* wv    = (const float*)d_in[7];
    const float* bv    = (const float*)d_in[8];
    const float* wp    = (const float*)d_in[9];
    const float* bp    = (const float*)d_in[10];
    float* out = (float*)d_out;

    float *xn, *q, *k, *v, *o, *vt, *wt, *attn;
    cudaGetSymbolAddress((void**)&xn,   g_xn);
    cudaGetSymbolAddress((void**)&q,    g_q);
    cudaGetSymbolAddress((void**)&k,    g_k);
    cudaGetSymbolAddress((void**)&v,    g_v);
    cudaGetSymbolAddress((void**)&o,    g_o);
    cudaGetSymbolAddress((void**)&vt,   g_vt);
    cudaGetSymbolAddress((void**)&wt,   g_wt);
    cudaGetSymbolAddress((void**)&attn, g_attn);

    cudaFuncSetAttribute(gemm_mma, cudaFuncAttributeMaxDynamicSharedMemorySize, GEMM_SMEM);

    const float SCALE = 0.04419417382415922f;   // 1/sqrt(512)
    const size_t sQ = (size_t)4096 * 512;
    const size_t sS = (size_t)4096 * 4096;
    const size_t sW = (size_t)512 * 512;

    // GroupNorm
    gn_stats<<<64, 256>>>(x);
    gn_apply<<<4096, 256>>>(x, gamma, beta);

    // Weight transposes (512x512): wt[i] = w_i^T
    dim3 tb(32, 8);
    transpose_k<<<dim3(16, 16, 1), tb>>>(wq, wt + 0 * sW, 512, 512, 0, 0);
    transpose_k<<<dim3(16, 16, 1), tb>>>(wk, wt + 1 * sW, 512, 512, 0, 0);
    transpose_k<<<dim3(16, 16, 1), tb>>>(wv, wt + 2 * sW, 512, 512, 0, 0);
    transpose_k<<<dim3(16, 16, 1), tb>>>(wp, wt + 3 * sW, 512, 512, 0, 0);

    // QKV: [8192,512] = xn @ w^T (NT), + bias
    dim3 gQKV(512 / BN, 8192 / BM, 1);
    gemm_mma<<<gQKV, 256, GEMM_SMEM>>>(xn, wt + 0 * sW, q, bq, nullptr, 8192, 512, 512, 1.f, 0, 0, 0);
    gemm_mma<<<gQKV, 256, GEMM_SMEM>>>(xn, wt + 1 * sW, k, bk, nullptr, 8192, 512, 512, 1.f, 0, 0, 0);
    gemm_mma<<<gQKV, 256, GEMM_SMEM>>>(xn, wt + 2 * sW, v, bv, nullptr, 8192, 512, 512, 1.f, 0, 0, 0);

    // S = scale * Q @ K^T per batch
    dim3 gS(4096 / BN, 4096 / BM, 2);
    gemm_mma<<<gS, 256, GEMM_SMEM>>>(q, k, attn, nullptr, nullptr, 4096, 4096, 512, SCALE, sQ, sQ, sS);

    // softmax rows
    softmax4096<<<8192, 256>>>(attn);

    // V^T per batch: [512,4096]
    transpose_k<<<dim3(16, 128, 2), tb>>>(v, vt, 4096, 512, sQ, sQ);

    // O = P @ V = P @ (V^T)^T  (NT with B = V^T)
    dim3 gPV(512 / BN, 4096 / BM, 2);
    gemm_mma<<<gPV, 256, GEMM_SMEM>>>(attn, vt, o, nullptr, nullptr, 4096, 512, 4096, 1.f, sS, sQ, sQ);

    // out = O @ wp^T (NT) + bp + x
    dim3 gP(512 / BN, 8192 / BM, 1);
    gemm_mma<<<gP, 256, GEMM_SMEM>>>(o, wt + 3 * sW, out, bp, x, 8192, 512, 512, 1.f, 0, 0, 0);
}

// round 12
// speedup vs baseline: 3.4591x; 1.0011x over previous
#include <cuda_runtime.h>
#include <cstdint>
#include <cstddef>

// ---------------------------------------------------------------------------
// AttentionBlock via mma.sync tf32 (HMMA path — tcgen05 PTX is rejected because
// the harness PTX target is plain sm_103, not sm_103a).
//   GroupNorm(32) -> QKV -> softmax(QK^T/sqrt(C)) V -> proj + residual
//   B=2, N_tok=4096, C=512, fp32 I/O.
// All GEMMs are NT: D[m,n] = sum_k A[m,k]*B[n,k]; weights / V pre-transposed.
// ---------------------------------------------------------------------------

typedef unsigned long long u64;

// ---------------- GEMM tile config ----------------
#define BM 128
#define BN 128
#define BK 32                       // fp32 elements per chunk (4 MMA k-steps of 8)
#define NST 3                       // cp.async pipeline stages
#define LDSTR 36                    // padded row stride in floats (32 -> 36)
#define A_FLOATS (BM * LDSTR)       // 4608 floats per A tile
#define STG_FLOATS (2 * A_FLOATS)   // 9216 floats per stage (A + B)
#define GEMM_SMEM (NST * STG_FLOATS * 4)   // 110592 bytes

// ---------------- scratch (allocation-free) ----------------
__device__ float g_xn  [8192 * 512];
__device__ float g_q   [8192 * 512];
__device__ float g_k   [8192 * 512];
__device__ float g_v   [8192 * 512];
__device__ float g_o   [8192 * 512];
__device__ float g_vt  [8192 * 512];                 // V^T per batch: [512,4096]
__device__ float g_wt  [4 * 512 * 512];              // wq^T, wk^T, wv^T, wp^T
__device__ float g_attn[(size_t)2 * 4096 * 4096];
__device__ float g_mean[64];
__device__ float g_rstd[64];

// ---------------- helpers ----------------
__device__ __forceinline__ uint32_t smem_u32(const void* p) {
    uint32_t a;
    asm("{ .reg .u64 t; cvta.to.shared.u64 t, %1; cvt.u32.u64 %0, t; }" : "=r"(a) : "l"(p));
    return a;
}
__device__ __forceinline__ void cpa16(uint32_t dst, const float* src) {
    asm volatile("cp.async.cg.shared.global [%0], [%1], 16;" :: "r"(dst), "l"(src));
}

// ---------------------------------------------------------------------------
// GroupNorm
// ---------------------------------------------------------------------------
__global__ void gn_stats(const float* __restrict__ x) {
    int bg = blockIdx.x, b = bg >> 5, g = bg & 31;
    const float* base = x + (size_t)b * 4096 * 512 + g * 16;
    float s = 0.f, ss = 0.f;
    for (int i = threadIdx.x; i < 65536; i += 256) {
        int p = i >> 4, c = i & 15;
        float v = base[(size_t)p * 512 + c];
        s += v; ss += v * v;
    }
    __shared__ float sh1[256], sh2[256];
    sh1[threadIdx.x] = s; sh2[threadIdx.x] = ss;
    __syncthreads();
    for (int st = 128; st > 0; st >>= 1) {
        if (threadIdx.x < st) {
            sh1[threadIdx.x] += sh1[threadIdx.x + st];
            sh2[threadIdx.x] += sh2[threadIdx.x + st];
        }
        __syncthreads();
    }
    if (threadIdx.x == 0) {
        float m = sh1[0] * (1.f / 65536.f);
        float var = sh2[0] * (1.f / 65536.f) - m * m;
        g_mean[bg] = m;
        g_rstd[bg] = rsqrtf(var + 1e-5f);
    }
}

__global__ void gn_apply(const float* __restrict__ x,
                         const float* __restrict__ gamma,
                         const float* __restrict__ beta) {
    size_t e = ((size_t)blockIdx.x * blockDim.x + threadIdx.x) * 4;
    int c = (int)(e & 511);
    int b = (int)(e >> 21);
    int bg = b * 32 + (c >> 4);
    float m = g_mean[bg], r = g_rstd[bg];
    float4 xv = *(const float4*)(x + e);
    float4 o;
    o.x = (xv.x - m) * r * gamma[c + 0] + beta[c + 0];
    o.y = (xv.y - m) * r * gamma[c + 1] + beta[c + 1];
    o.z = (xv.z - m) * r * gamma[c + 2] + beta[c + 2];
    o.w = (xv.w - m) * r * gamma[c + 3] + beta[c + 3];
    *(float4*)(g_xn + e) = o;
}

// ---------------------------------------------------------------------------
// Transpose: out[b][c][r] = in[b][r][c].  grid(C/32, R/32, batch), block(32,8)
// ---------------------------------------------------------------------------
__global__ void transpose_k(const float* __restrict__ in, float* __restrict__ out,
                            int R, int C, size_t sIn, size_t sOut) {
    in  += (size_t)blockIdx.z * sIn;
    out += (size_t)blockIdx.z * sOut;
    __shared__ float t[32][33];
    int c0 = blockIdx.x * 32, r0 = blockIdx.y * 32;
    int tx = threadIdx.x, ty = threadIdx.y;
#pragma unroll
    for (int i = 0; i < 32; i += 8)
        t[ty + i][tx] = in[(size_t)(r0 + ty + i) * C + c0 + tx];
    __syncthreads();
#pragma unroll
    for (int i = 0; i < 32; i += 8)
        out[(size_t)(c0 + ty + i) * R + r0 + tx] = t[tx][ty + i];
}

// ---------------------------------------------------------------------------
// tf32 mma.sync GEMM (NT): D = scale*(A @ B^T) + bias + residual
//   A [M,K] row-major, B [N,K] row-major, D [M,N] row-major.
//   CTA tile 128x128x32, 8 warps (2m x 4n), warp tile 64x32, mma m16n8k8.
//   grid(N/128, M/128, batch), 256 threads, 3-stage cp.async pipeline.
// ---------------------------------------------------------------------------
__global__ void __launch_bounds__(256, 2)
gemm_mma(const float* __restrict__ A, const float* __restrict__ B,
         float* __restrict__ C, const float* __restrict__ bias,
         const float* __restrict__ residual,
         int M, int N, int K, float scale,
         size_t sA, size_t sB, size_t sC) {
    extern __shared__ float smem[];
    const uint32_t saddr = smem_u32(smem);
    const int tid = threadIdx.x;
    const int wid = tid >> 5, lid = tid & 31;
    const int gid = lid >> 2, tig = lid & 3;     // quad row / thread-in-group
    const int wm  = wid >> 2, wn  = wid & 3;     // warp grid 2x4

    const int row0 = blockIdx.y * BM;
    const int col0 = blockIdx.x * BN;
    const float* Ab = A + (size_t)blockIdx.z * sA + (size_t)row0 * K;
    const float* Bb = B + (size_t)blockIdx.z * sB + (size_t)col0 * K;

    float acc[4][4][4];
#pragma unroll
    for (int i = 0; i < 4; i++)
#pragma unroll
        for (int j = 0; j < 4; j++)
#pragma unroll
            for (int r = 0; r < 4; r++) acc[i][j][r] = 0.f;

    const int nch = K / BK;

    auto load_stage = [&](int s, int kt) {
        uint32_t dA = saddr + (uint32_t)(s * STG_FLOATS) * 4u;
        uint32_t dB = dA + (uint32_t)A_FLOATS * 4u;
        const float* Ak = Ab + kt * BK;
        const float* Bk = Bb + kt * BK;
#pragma unroll
        for (int i = 0; i < 4; i++) {            // A: 128 rows x 8 x 16B
            int idx = tid + 256 * i;
            int r = idx >> 3, e = idx & 7;
            cpa16(dA + (uint32_t)(r * LDSTR + e * 4) * 4u, Ak + (size_t)r * K + e * 4);
        }
#pragma unroll
        for (int i = 0; i < 4; i++) {            // B: 128 rows x 8 x 16B
            int idx = tid + 256 * i;
            int r = idx >> 3, e = idx & 7;
            cpa16(dB + (uint32_t)(r * LDSTR + e * 4) * 4u, Bk + (size_t)r * K + e * 4);
        }
        asm volatile("cp.async.commit_group;" ::: "memory");
    };

    // prologue: stages 0,1 (nch >= 16 always here)
    load_stage(0, 0);
    load_stage(1, 1);

    for (int kt = 0; kt < nch; kt++) {
        int s = kt % NST;
        if (kt == nch - 1) asm volatile("cp.async.wait_group 0;" ::: "memory");
        else               asm volatile("cp.async.wait_group 1;" ::: "memory");
        __syncthreads();

        const uint32_t* As = (const uint32_t*)(smem + s * STG_FLOATS);
        const uint32_t* Bs = As + A_FLOATS;

#pragma unroll
        for (int ks = 0; ks < 4; ks++) {
            const int kb = ks * 8;
            uint32_t a[4][4], b[4][2];
#pragma unroll
            for (int mt = 0; mt < 4; mt++) {
                int r = wm * 64 + mt * 16 + gid;
                a[mt][0] = As[r * LDSTR + kb + tig];
                a[mt][1] = As[(r + 8) * LDSTR + kb + tig];
                a[mt][2] = As[r * LDSTR + kb + tig + 4];
                a[mt][3] = As[(r + 8) * LDSTR + kb + tig + 4];
            }
#pragma unroll
            for (int nt = 0; nt < 4; nt++) {
                int n = wn * 32 + nt * 8 + gid;
                b[nt][0] = Bs[n * LDSTR + kb + tig];
                b[nt][1] = Bs[n * LDSTR + kb + tig + 4];
            }
#pragma unroll
            for (int mt = 0; mt < 4; mt++)
#pragma unroll
                for (int nt = 0; nt < 4; nt++)
                    asm volatile(
                        "mma.sync.aligned.m16n8k8.row.col.f32.tf32.tf32.f32 "
                        "{%0,%1,%2,%3}, {%4,%5,%6,%7}, {%8,%9}, {%0,%1,%2,%3};"
                        : "+f"(acc[mt][nt][0]), "+f"(acc[mt][nt][1]),
                          "+f"(acc[mt][nt][2]), "+f"(acc[mt][nt][3])
                        : "r"(a[mt][0]), "r"(a[mt][1]), "r"(a[mt][2]), "r"(a[mt][3]),
                          "r"(b[nt][0]), "r"(b[nt][1]));
        }
        __syncthreads();
        if (kt + 2 < nch) load_stage((kt + 2) % NST, kt + 2);
    }

    // epilogue
    float* Cb = C + (size_t)blockIdx.z * sC;
    const float* Rb = residual ? residual + (size_t)blockIdx.z * sC : nullptr;
#pragma unroll
    for (int mt = 0; mt < 4; mt++) {
        int r = row0 + wm * 64 + mt * 16 + gid;
#pragma unroll
        for (int nt = 0; nt < 4; nt++) {
            int c = col0 + wn * 32 + nt * 8 + 2 * tig;
#pragma unroll
            for (int h = 0; h < 2; h++) {
                int rr = r + h * 8;
                float v0 = acc[mt][nt][2 * h + 0] * scale;
                float v1 = acc[mt][nt][2 * h + 1] * scale;
                if (bias) { v0 += bias[c]; v1 += bias[c + 1]; }
                if (Rb) {
                    float2 rv = *(const float2*)(Rb + (size_t)rr * N + c);
                    v0 += rv.x; v1 += rv.y;
                }
                *(float2*)(Cb + (size_t)rr * N + c) = make_float2(v0, v1);
            }
        }
    }
}

// ---------------------------------------------------------------------------
// Row softmax, length 4096, one 256-thread block per row, in-place.
// ---------------------------------------------------------------------------
__global__ void softmax4096(float* __restrict__ S) {
    float* p = S + (size_t)blockIdx.x * 4096;
    const int t = threadIdx.x;
    __shared__ float sh[8];

    float v[16];
    float mx = -1e30f;
#pragma unroll
    for (int i = 0; i < 16; i++) {
        v[i] = p[t + i * 256];
        mx = fmaxf(mx, v[i]);
    }
#pragma unroll
    for (int off = 16; off > 0; off >>= 1)
        mx = fmaxf(mx, __shfl_xor_sync(0xffffffffu, mx, off));
    if ((t & 31) == 0) sh[t >> 5] = mx;
    __syncthreads();
    {
        float m = sh[t & 7];
#pragma unroll
        for (int off = 4; off > 0; off >>= 1)
            m = fmaxf(m, __shfl_xor_sync(0xffffffffu, m, off));
        mx = m;
    }
    __syncthreads();

    float s = 0.f;
#pragma unroll
    for (int i = 0; i < 16; i++) {
        v[i] = __expf(v[i] - mx);
        s += v[i];
    }
#pragma unroll
    for (int off = 16; off > 0; off >>= 1)
        s += __shfl_xor_sync(0xffffffffu, s, off);
    if ((t & 31) == 0) sh[t >> 5] = s;
    __syncthreads();
    {
        float m = sh[t & 7];
#pragma unroll
        for (int off = 4; off > 0; off >>= 1)
            m += __shfl_xor_sync(0xffffffffu, m, off);
        s = m;
    }
    float inv = 1.f / s;
#pragma unroll
    for (int i = 0; i < 16; i++) p[t + i * 256] = v[i] * inv;
}

// ---------------------------------------------------------------------------
// Launch
// ---------------------------------------------------------------------------
extern "C" void kernel_launch(void* const* d_in, const int* in_sizes, int n_in,
                              void* d_out, int out_size) {
    (void)in_sizes; (void)n_in; (void)out_size;

    const float* x     = (const float*)d_in[0];
    const float* gamma = (const float*)d_in[1];
    const float* beta  = (const float*)d_in[2];
    const float* wq    = (const float*)d_in[3];
    const float* bq    = (const float*)d_in[4];
    const float* wk    = (const float*)d_in[5];
    const float* bk    = (const float*)d_in[6];
    const float* wv    = (const float*)d_in[7];
    const float* bv    = (const float*)d_in[8];
    const float* wp    = (const float*)d_in[9];
    const float* bp    = (const float*)d_in[10];
    float* out = (float*)d_out;

    float *xn, *q, *k, *v, *o, *vt, *wt, *attn;
    cudaGetSymbolAddress((void**)&xn,   g_xn);
    cudaGetSymbolAddress((void**)&q,    g_q);
    cudaGetSymbolAddress((void**)&k,    g_k);
    cudaGetSymbolAddress((void**)&v,    g_v);
    cudaGetSymbolAddress((void**)&o,    g_o);
    cudaGetSymbolAddress((void**)&vt,   g_vt);
    cudaGetSymbolAddress((void**)&wt,   g_wt);
    cudaGetSymbolAddress((void**)&attn, g_attn);

    cudaFuncSetAttribute(gemm_mma, cudaFuncAttributeMaxDynamicSharedMemorySize, GEMM_SMEM);

    const float SCALE = 0.04419417382415922f;   // 1/sqrt(512)
    const size_t sQ = (size_t)4096 * 512;
    const size_t sS = (size_t)4096 * 4096;
    const size_t sW = (size_t)512 * 512;

    // GroupNorm
    gn_stats<<<64, 256>>>(x);
    gn_apply<<<4096, 256>>>(x, gamma, beta);

    // Weight transposes (512x512): wt[i] = w_i^T
    dim3 tb(32, 8);
    transpose_k<<<dim3(16, 16, 1), tb>>>(wq, wt + 0 * sW, 512, 512, 0, 0);
    transpose_k<<<dim3(16, 16, 1), tb>>>(wk, wt + 1 * sW, 512, 512, 0, 0);
    transpose_k<<<dim3(16, 16, 1), tb>>>(wv, wt + 2 * sW, 512, 512, 0, 0);
    transpose_k<<<dim3(16, 16, 1), tb>>>(wp, wt + 3 * sW, 512, 512, 0, 0);

    // QKV: [8192,512] = xn @ w^T (NT), + bias
    dim3 gQKV(512 / BN, 8192 / BM, 1);
    gemm_mma<<<gQKV, 256, GEMM_SMEM>>>(xn, wt + 0 * sW, q, bq, nullptr, 8192, 512, 512, 1.f, 0, 0, 0);
    gemm_mma<<<gQKV, 256, GEMM_SMEM>>>(xn, wt + 1 * sW, k, bk, nullptr, 8192, 512, 512, 1.f, 0, 0, 0);
    gemm_mma<<<gQKV, 256, GEMM_SMEM>>>(xn, wt + 2 * sW, v, bv, nullptr, 8192, 512, 512, 1.f, 0, 0, 0);

    // S = scale * Q @ K^T per batch
    dim3 gS(4096 / BN, 4096 / BM, 2);
    gemm_mma<<<gS, 256, GEMM_SMEM>>>(q, k, attn, nullptr, nullptr, 4096, 4096, 512, SCALE, sQ, sQ, sS);

    // softmax rows
    softmax4096<<<8192, 256>>>(attn);

    // V^T per batch: [512,4096]
    transpose_k<<<dim3(16, 128, 2), tb>>>(v, vt, 4096, 512, sQ, sQ);

    // O = P @ V = P @ (V^T)^T  (NT with B = V^T)
    dim3 gPV(512 / BN, 4096 / BM, 2);
    gemm_mma<<<gPV, 256, GEMM_SMEM>>>(attn, vt, o, nullptr, nullptr, 4096, 512, 4096, 1.f, sS, sQ, sQ);

    // out = O @ wp^T (NT) + bp + x
    dim3 gP(512 / BN, 8192 / BM, 1);
    gemm_mma<<<gP, 256, GEMM_SMEM>>>(o, wt + 3 * sW, out, bp, x, 8192, 512, 512, 1.f, 0, 0, 0);
}

// round 13
// speedup vs baseline: 3.4648x; 1.0016x over previous
#include <cuda_runtime.h>
#include <cstdint>
#include <cstddef>

// ---------------------------------------------------------------------------
// AttentionBlock via mma.sync tf32 (HMMA path — tcgen05 PTX is rejected because
// the harness PTX target is plain sm_103, not sm_103a).
//   GroupNorm(32) -> QKV -> softmax(QK^T/sqrt(C)) V -> proj + residual
//   B=2, N_tok=4096, C=512, fp32 I/O.
// All GEMMs are NT: D[m,n] = sum_k A[m,k]*B[n,k]; weights / V pre-transposed.
// ---------------------------------------------------------------------------

typedef unsigned long long u64;

// ---------------- GEMM tile config ----------------
#define BM 128
#define BN 128
#define BK 32                       // fp32 elements per chunk (4 MMA k-steps of 8)
#define NST 3                       // cp.async pipeline stages
#define LDSTR 36                    // padded row stride in floats (32 -> 36)
#define A_FLOATS (BM * LDSTR)       // 4608 floats per A tile
#define STG_FLOATS (2 * A_FLOATS)   // 9216 floats per stage (A + B)
#define GEMM_SMEM (NST * STG_FLOATS * 4)   // 110592 bytes

// ---------------- scratch (allocation-free) ----------------
__device__ float g_xn  [8192 * 512];
__device__ float g_q   [8192 * 512];
__device__ float g_k   [8192 * 512];
__device__ float g_v   [8192 * 512];
__device__ float g_o   [8192 * 512];
__device__ float g_vt  [8192 * 512];                 // V^T per batch: [512,4096]
__device__ float g_wt  [4 * 512 * 512];              // wq^T, wk^T, wv^T, wp^T
__device__ float g_attn[(size_t)2 * 4096 * 4096];
__device__ float g_mean[64];
__device__ float g_rstd[64];

// ---------------- helpers ----------------
__device__ __forceinline__ uint32_t smem_u32(const void* p) {
    uint32_t a;
    asm("{ .reg .u64 t; cvta.to.shared.u64 t, %1; cvt.u32.u64 %0, t; }" : "=r"(a) : "l"(p));
    return a;
}
__device__ __forceinline__ void cpa16(uint32_t dst, const float* src) {
    asm volatile("cp.async.cg.shared.global [%0], [%1], 16;" :: "r"(dst), "l"(src));
}

// ---------------------------------------------------------------------------
// GroupNorm
// ---------------------------------------------------------------------------
__global__ void gn_stats(const float* __restrict__ x) {
    int bg = blockIdx.x, b = bg >> 5, g = bg & 31;
    const float* base = x + (size_t)b * 4096 * 512 + g * 16;
    float s = 0.f, ss = 0.f;
    for (int i = threadIdx.x; i < 65536; i += 256) {
        int p = i >> 4, c = i & 15;
        float v = base[(size_t)p * 512 + c];
        s += v; ss += v * v;
    }
    __shared__ float sh1[256], sh2[256];
    sh1[threadIdx.x] = s; sh2[threadIdx.x] = ss;
    __syncthreads();
    for (int st = 128; st > 0; st >>= 1) {
        if (threadIdx.x < st) {
            sh1[threadIdx.x] += sh1[threadIdx.x + st];
            sh2[threadIdx.x] += sh2[threadIdx.x + st];
        }
        __syncthreads();
    }
    if (threadIdx.x == 0) {
        float m = sh1[0] * (1.f / 65536.f);
        float var = sh2[0] * (1.f / 65536.f) - m * m;
        g_mean[bg] = m;
        g_rstd[bg] = rsqrtf(var + 1e-5f);
    }
}

__global__ void gn_apply(const float* __restrict__ x,
                         const float* __restrict__ gamma,
                         const float* __restrict__ beta) {
    size_t e = ((size_t)blockIdx.x * blockDim.x + threadIdx.x) * 4;
    int c = (int)(e & 511);
    int b = (int)(e >> 21);
    int bg = b * 32 + (c >> 4);
    float m = g_mean[bg], r = g_rstd[bg];
    float4 xv = *(const float4*)(x + e);
    float4 o;
    o.x = (xv.x - m) * r * gamma[c + 0] + beta[c + 0];
    o.y = (xv.y - m) * r * gamma[c + 1] + beta[c + 1];
    o.z = (xv.z - m) * r * gamma[c + 2] + beta[c + 2];
    o.w = (xv.w - m) * r * gamma[c + 3] + beta[c + 3];
    *(float4*)(g_xn + e) = o;
}

// ---------------------------------------------------------------------------
// Transpose: out[b][c][r] = in[b][r][c].  grid(C/32, R/32, batch), block(32,8)
// ---------------------------------------------------------------------------
__global__ void transpose_k(const float* __restrict__ in, float* __restrict__ out,
                            int R, int C, size_t sIn, size_t sOut) {
    in  += (size_t)blockIdx.z * sIn;
    out += (size_t)blockIdx.z * sOut;
    __shared__ float t[32][33];
    int c0 = blockIdx.x * 32, r0 = blockIdx.y * 32;
    int tx = threadIdx.x, ty = threadIdx.y;
#pragma unroll
    for (int i = 0; i < 32; i += 8)
        t[ty + i][tx] = in[(size_t)(r0 + ty + i) * C + c0 + tx];
    __syncthreads();
#pragma unroll
    for (int i = 0; i < 32; i += 8)
        out[(size_t)(c0 + ty + i) * R + r0 + tx] = t[tx][ty + i];
}

// ---------------------------------------------------------------------------
// tf32 mma.sync GEMM (NT): D = scale*(A @ B^T) + bias + residual
//   A [M,K] row-major, B [N,K] row-major, D [M,N] row-major.
//   CTA tile 128x128x32, 8 warps (2m x 4n), warp tile 64x32, mma m16n8k8.
//   grid(N/128, M/128, batch), 256 threads, 3-stage cp.async pipeline.
// ---------------------------------------------------------------------------
__global__ void __launch_bounds__(256, 2)
gemm_mma(const float* __restrict__ A, const float* __restrict__ B,
         float* __restrict__ C, const float* __restrict__ bias,
         const float* __restrict__ residual,
         int M, int N, int K, float scale,
         size_t sA, size_t sB, size_t sC) {
    extern __shared__ float smem[];
    const uint32_t saddr = smem_u32(smem);
    const int tid = threadIdx.x;
    const int wid = tid >> 5, lid = tid & 31;
    const int gid = lid >> 2, tig = lid & 3;     // quad row / thread-in-group
    const int wm  = wid >> 2, wn  = wid & 3;     // warp grid 2x4

    const int row0 = blockIdx.y * BM;
    const int col0 = blockIdx.x * BN;
    const float* Ab = A + (size_t)blockIdx.z * sA + (size_t)row0 * K;
    const float* Bb = B + (size_t)blockIdx.z * sB + (size_t)col0 * K;

    float acc[4][4][4];
#pragma unroll
    for (int i = 0; i < 4; i++)
#pragma unroll
        for (int j = 0; j < 4; j++)
#pragma unroll
            for (int r = 0; r < 4; r++) acc[i][j][r] = 0.f;

    const int nch = K / BK;

    auto load_stage = [&](int s, int kt) {
        uint32_t dA = saddr + (uint32_t)(s * STG_FLOATS) * 4u;
        uint32_t dB = dA + (uint32_t)A_FLOATS * 4u;
        const float* Ak = Ab + kt * BK;
        const float* Bk = Bb + kt * BK;
#pragma unroll
        for (int i = 0; i < 4; i++) {            // A: 128 rows x 8 x 16B
            int idx = tid + 256 * i;
            int r = idx >> 3, e = idx & 7;
            cpa16(dA + (uint32_t)(r * LDSTR + e * 4) * 4u, Ak + (size_t)r * K + e * 4);
        }
#pragma unroll
        for (int i = 0; i < 4; i++) {            // B: 128 rows x 8 x 16B
            int idx = tid + 256 * i;
            int r = idx >> 3, e = idx & 7;
            cpa16(dB + (uint32_t)(r * LDSTR + e * 4) * 4u, Bk + (size_t)r * K + e * 4);
        }
        asm volatile("cp.async.commit_group;" ::: "memory");
    };

    // prologue: stages 0,1 (nch >= 16 always here)
    load_stage(0, 0);
    load_stage(1, 1);

    for (int kt = 0; kt < nch; kt++) {
        int s = kt % NST;
        if (kt == nch - 1) asm volatile("cp.async.wait_group 0;" ::: "memory");
        else               asm volatile("cp.async.wait_group 1;" ::: "memory");
        __syncthreads();

        const uint32_t* As = (const uint32_t*)(smem + s * STG_FLOATS);
        const uint32_t* Bs = As + A_FLOATS;

#pragma unroll
        for (int ks = 0; ks < 4; ks++) {
            const int kb = ks * 8;
            uint32_t a[4][4], b[4][2];
#pragma unroll
            for (int mt = 0; mt < 4; mt++) {
                int r = wm * 64 + mt * 16 + gid;
                a[mt][0] = As[r * LDSTR + kb + tig];
                a[mt][1] = As[(r + 8) * LDSTR + kb + tig];
                a[mt][2] = As[r * LDSTR + kb + tig + 4];
                a[mt][3] = As[(r + 8) * LDSTR + kb + tig + 4];
            }
#pragma unroll
            for (int nt = 0; nt < 4; nt++) {
                int n = wn * 32 + nt * 8 + gid;
                b[nt][0] = Bs[n * LDSTR + kb + tig];
                b[nt][1] = Bs[n * LDSTR + kb + tig + 4];
            }
#pragma unroll
            for (int mt = 0; mt < 4; mt++)
#pragma unroll
                for (int nt = 0; nt < 4; nt++)
                    asm volatile(
                        "mma.sync.aligned.m16n8k8.row.col.f32.tf32.tf32.f32 "
                        "{%0,%1,%2,%3}, {%4,%5,%6,%7}, {%8,%9}, {%0,%1,%2,%3};"
                        : "+f"(acc[mt][nt][0]), "+f"(acc[mt][nt][1]),
                          "+f"(acc[mt][nt][2]), "+f"(acc[mt][nt][3])
                        : "r"(a[mt][0]), "r"(a[mt][1]), "r"(a[mt][2]), "r"(a[mt][3]),
                          "r"(b[nt][0]), "r"(b[nt][1]));
        }
        __syncthreads();
        if (kt + 2 < nch) load_stage((kt + 2) % NST, kt + 2);
    }

    // epilogue
    float* Cb = C + (size_t)blockIdx.z * sC;
    const float* Rb = residual ? residual + (size_t)blockIdx.z * sC : nullptr;
#pragma unroll
    for (int mt = 0; mt < 4; mt++) {
        int r = row0 + wm * 64 + mt * 16 + gid;
#pragma unroll
        for (int nt = 0; nt < 4; nt++) {
            int c = col0 + wn * 32 + nt * 8 + 2 * tig;
#pragma unroll
            for (int h = 0; h < 2; h++) {
                int rr = r + h * 8;
                float v0 = acc[mt][nt][2 * h + 0] * scale;
                float v1 = acc[mt][nt][2 * h + 1] * scale;
                if (bias) { v0 += bias[c]; v1 += bias[c + 1]; }
                if (Rb) {
                    float2 rv = *(const float2*)(Rb + (size_t)rr * N + c);
                    v0 += rv.x; v1 += rv.y;
                }
                *(float2*)(Cb + (size_t)rr * N + c) = make_float2(v0, v1);
            }
        }
    }
}

// ---------------------------------------------------------------------------
// Row softmax, length 4096, one 256-thread block per row, in-place.
// ---------------------------------------------------------------------------
__global__ void softmax4096(float* __restrict__ S) {
    float* p = S + (size_t)blockIdx.x * 4096;
    const int t = threadIdx.x;
    __shared__ float sh[8];

    float v[16];
    float mx = -1e30f;
#pragma unroll
    for (int i = 0; i < 16; i++) {
        v[i] = p[t + i * 256];
        mx = fmaxf(mx, v[i]);
    }
#pragma unroll
    for (int off = 16; off > 0; off >>= 1)
        mx = fmaxf(mx, __shfl_xor_sync(0xffffffffu, mx, off));
    if ((t & 31) == 0) sh[t >> 5] = mx;
    __syncthreads();
    {
        float m = sh[t & 7];
#pragma unroll
        for (int off = 4; off > 0; off >>= 1)
            m = fmaxf(m, __shfl_xor_sync(0xffffffffu, m, off));
        mx = m;
    }
    __syncthreads();

    float s = 0.f;
#pragma unroll
    for (int i = 0; i < 16; i++) {
        v[i] = __expf(v[i] - mx);
        s += v[i];
    }
#pragma unroll
    for (int off = 16; off > 0; off >>= 1)
        s += __shfl_xor_sync(0xffffffffu, s, off);
    if ((t & 31) == 0) sh[t >> 5] = s;
    __syncthreads();
    {
        float m = sh[t & 7];
#pragma unroll
        for (int off = 4; off > 0; off >>= 1)
            m += __shfl_xor_sync(0xffffffffu, m, off);
        s = m;
    }
    float inv = 1.f / s;
#pragma unroll
    for (int i = 0; i < 16; i++) p[t + i * 256] = v[i] * inv;
}

// ---------------------------------------------------------------------------
// Launch
// ---------------------------------------------------------------------------
extern "C" void kernel_launch(void* const* d_in, const int* in_sizes, int n_in,
                              void* d_out, int out_size) {
    (void)in_sizes; (void)n_in; (void)out_size;

    const float* x     = (const float*)d_in[0];
    const float* gamma = (const float*)d_in[1];
    const float* beta  = (const float*)d_in[2];
    const float* wq    = (const float*)d_in[3];
    const float* bq    = (const float*)d_in[4];
    const float* wk    = (const float*)d_in[5];
    const float* bk    = (const float*)d_in[6];
    const float* wv    = (const float*)d_in[7];
    const float* bv    = (const float*)d_in[8];
    const float* wp    = (const float*)d_in[9];
    const float* bp    = (const float*)d_in[10];
    float* out = (float*)d_out;

    float *xn, *q, *k, *v, *o, *vt, *wt, *attn;
    cudaGetSymbolAddress((void**)&xn,   g_xn);
    cudaGetSymbolAddress((void**)&q,    g_q);
    cudaGetSymbolAddress((void**)&k,    g_k);
    cudaGetSymbolAddress((void**)&v,    g_v);
    cudaGetSymbolAddress((void**)&o,    g_o);
    cudaGetSymbolAddress((void**)&vt,   g_vt);
    cudaGetSymbolAddress((void**)&wt,   g_wt);
    cudaGetSymbolAddress((void**)&attn, g_attn);

    cudaFuncSetAttribute(gemm_mma, cudaFuncAttributeMaxDynamicSharedMemorySize, GEMM_SMEM);

    const float SCALE = 0.04419417382415922f;   // 1/sqrt(512)
    const size_t sQ = (size_t)4096 * 512;
    const size_t sS = (size_t)4096 * 4096;
    const size_t sW = (size_t)512 * 512;

    // GroupNorm
    gn_stats<<<64, 256>>>(x);
    gn_apply<<<4096, 256>>>(x, gamma, beta);

    // Weight transposes (512x512): wt[i] = w_i^T
    dim3 tb(32, 8);
    transpose_k<<<dim3(16, 16, 1), tb>>>(wq, wt + 0 * sW, 512, 512, 0, 0);
    transpose_k<<<dim3(16, 16, 1), tb>>>(wk, wt + 1 * sW, 512, 512, 0, 0);
    transpose_k<<<dim3(16, 16, 1), tb>>>(wv, wt + 2 * sW, 512, 512, 0, 0);
    transpose_k<<<dim3(16, 16, 1), tb>>>(wp, wt + 3 * sW, 512, 512, 0, 0);

    // QKV: [8192,512] = xn @ w^T (NT), + bias
    dim3 gQKV(512 / BN, 8192 / BM, 1);
    gemm_mma<<<gQKV, 256, GEMM_SMEM>>>(xn, wt + 0 * sW, q, bq, nullptr, 8192, 512, 512, 1.f, 0, 0, 0);
    gemm_mma<<<gQKV, 256, GEMM_SMEM>>>(xn, wt + 1 * sW, k, bk, nullptr, 8192, 512, 512, 1.f, 0, 0, 0);
    gemm_mma<<<gQKV, 256, GEMM_SMEM>>>(xn, wt + 2 * sW, v, bv, nullptr, 8192, 512, 512, 1.f, 0, 0, 0);

    // S = scale * Q @ K^T per batch
    dim3 gS(4096 / BN, 4096 / BM, 2);
    gemm_mma<<<gS, 256, GEMM_SMEM>>>(q, k, attn, nullptr, nullptr, 4096, 4096, 512, SCALE, sQ, sQ, sS);

    // softmax rows
    softmax4096<<<8192, 256>>>(attn);

    // V^T per batch: [512,4096]
    transpose_k<<<dim3(16, 128, 2), tb>>>(v, vt, 4096, 512, sQ, sQ);

    // O = P @ V = P @ (V^T)^T  (NT with B = V^T)
    dim3 gPV(512 / BN, 4096 / BM, 2);
    gemm_mma<<<gPV, 256, GEMM_SMEM>>>(attn, vt, o, nullptr, nullptr, 4096, 512, 4096, 1.f, sS, sQ, sQ);

    // out = O @ wp^T (NT) + bp + x
    dim3 gP(512 / BN, 8192 / BM, 1);
    gemm_mma<<<gP, 256, GEMM_SMEM>>>(o, wt + 3 * sW, out, bp, x, 8192, 512, 512, 1.f, 0, 0, 0);
}

// round 14
// speedup vs baseline: 5.7686x; 1.6649x over previous
#include <cuda_runtime.h>
#include <cuda_bf16.h>
#include <cstdint>
#include <cstddef>

// ---------------------------------------------------------------------------
// AttentionBlock via mma.sync bf16 (m16n8k16 HMMA; tcgen05 PTX rejected: the
// harness PTX target is plain sm_103).
//   GroupNorm(32) -> QKV -> softmax(QK^T/sqrt(C)) V -> proj + residual
//   B=2, N_tok=4096, C=512.  fp32 I/O, bf16 GEMM operands, fp32 accum.
// All GEMMs are NT: D[m,n] = sum_k A[m,k]*B[n,k]; weights / V pre-transposed.
// ---------------------------------------------------------------------------

typedef unsigned long long u64;
typedef __nv_bfloat16  bf16;
typedef __nv_bfloat162 bf162;

// ---------------- GEMM tile config ----------------
#define BM 128
#define BN 128
#define BKH 64                       // bf16 elements per K-chunk (4 mma k-steps of 16)
#define NST 3                        // cp.async pipeline stages
#define PITCH 72                     // padded row pitch in bf16 elems (144 B)
#define A_HALFS (BM * PITCH)         // 9216
#define STG_HALFS (2 * A_HALFS)      // 18432 bf16 per stage (A + B)
#define GEMM_SMEM (NST * STG_HALFS * 2)   // 110592 bytes -> 2 CTA/SM

// ---------------- scratch (allocation-free) ----------------
__device__ bf16  h_xn [8192 * 512];
__device__ bf16  h_q  [8192 * 512];
__device__ bf16  h_k  [8192 * 512];
__device__ bf16  h_v  [8192 * 512];
__device__ bf16  h_vt [8192 * 512];                 // V^T per batch: [512,4096]
__device__ bf16  h_o  [8192 * 512];
__device__ bf16  h_wt [4 * 512 * 512];              // wq^T, wk^T, wv^T, wp^T (bf16)
__device__ bf16  h_attn[(size_t)2 * 4096 * 4096];
__device__ float g_mean[64];
__device__ float g_rstd[64];

// ---------------- helpers ----------------
__device__ __forceinline__ uint32_t smem_u32(const void* p) {
    uint32_t a;
    asm("{ .reg .u64 t; cvta.to.shared.u64 t, %1; cvt.u32.u64 %0, t; }" : "=r"(a) : "l"(p));
    return a;
}
__device__ __forceinline__ void cpa16(uint32_t dst, const void* src) {
    asm volatile("cp.async.cg.shared.global [%0], [%1], 16;" :: "r"(dst), "l"(src));
}

// ---------------------------------------------------------------------------
// GroupNorm
// ---------------------------------------------------------------------------
__global__ void gn_stats(const float* __restrict__ x) {
    int bg = blockIdx.x, b = bg >> 5, g = bg & 31;
    const float* base = x + (size_t)b * 4096 * 512 + g * 16;
    float s = 0.f, ss = 0.f;
    for (int i = threadIdx.x; i < 65536; i += 256) {
        int p = i >> 4, c = i & 15;
        float v = base[(size_t)p * 512 + c];
        s += v; ss += v * v;
    }
    __shared__ float sh1[256], sh2[256];
    sh1[threadIdx.x] = s; sh2[threadIdx.x] = ss;
    __syncthreads();
    for (int st = 128; st > 0; st >>= 1) {
        if (threadIdx.x < st) {
            sh1[threadIdx.x] += sh1[threadIdx.x + st];
            sh2[threadIdx.x] += sh2[threadIdx.x + st];
        }
        __syncthreads();
    }
    if (threadIdx.x == 0) {
        float m = sh1[0] * (1.f / 65536.f);
        float var = sh2[0] * (1.f / 65536.f) - m * m;
        g_mean[bg] = m;
        g_rstd[bg] = rsqrtf(var + 1e-5f);
    }
}

__global__ void gn_apply(const float* __restrict__ x,
                         const float* __restrict__ gamma,
                         const float* __restrict__ beta,
                         bf16* __restrict__ xn) {
    size_t e = ((size_t)blockIdx.x * blockDim.x + threadIdx.x) * 4;
    int c = (int)(e & 511);
    int b = (int)(e >> 21);
    int bg = b * 32 + (c >> 4);
    float m = g_mean[bg], r = g_rstd[bg];
    float4 xv = *(const float4*)(x + e);
    float o0 = (xv.x - m) * r * gamma[c + 0] + beta[c + 0];
    float o1 = (xv.y - m) * r * gamma[c + 1] + beta[c + 1];
    float o2 = (xv.z - m) * r * gamma[c + 2] + beta[c + 2];
    float o3 = (xv.w - m) * r * gamma[c + 3] + beta[c + 3];
    bf162 p0; p0.x = __float2bfloat16(o0); p0.y = __float2bfloat16(o1);
    bf162 p1; p1.x = __float2bfloat16(o2); p1.y = __float2bfloat16(o3);
    *(bf162*)(xn + e)     = p0;
    *(bf162*)(xn + e + 2) = p1;
}

// ---------------------------------------------------------------------------
// Transposes
// ---------------------------------------------------------------------------
// fp32 [R,C] -> bf16 [C,R]   (weights, 512x512)
__global__ void transpose_f2h(const float* __restrict__ in, bf16* __restrict__ out,
                              int R, int C) {
    __shared__ float t[32][33];
    int c0 = blockIdx.x * 32, r0 = blockIdx.y * 32;
    int tx = threadIdx.x, ty = threadIdx.y;
#pragma unroll
    for (int i = 0; i < 32; i += 8)
        t[ty + i][tx] = in[(size_t)(r0 + ty + i) * C + c0 + tx];
    __syncthreads();
#pragma unroll
    for (int i = 0; i < 32; i += 8)
        out[(size_t)(c0 + ty + i) * R + r0 + tx] = __float2bfloat16(t[tx][ty + i]);
}

// bf16 [R,C] -> bf16 [C,R] per batch (V^T)
__global__ void transpose_h(const bf16* __restrict__ in, bf16* __restrict__ out,
                            int R, int C, size_t sIn, size_t sOut) {
    in  += (size_t)blockIdx.z * sIn;
    out += (size_t)blockIdx.z * sOut;
    __shared__ bf16 t[32][34];
    int c0 = blockIdx.x * 32, r0 = blockIdx.y * 32;
    int tx = threadIdx.x, ty = threadIdx.y;
#pragma unroll
    for (int i = 0; i < 32; i += 8)
        t[ty + i][tx] = in[(size_t)(r0 + ty + i) * C + c0 + tx];
    __syncthreads();
#pragma unroll
    for (int i = 0; i < 32; i += 8)
        out[(size_t)(c0 + ty + i) * R + r0 + tx] = t[tx][ty + i];
}

// ---------------------------------------------------------------------------
// bf16 mma.sync GEMM (NT): D = scale*(A @ B^T) [+ bias] [+ residual]
//   A [M,K] row-major bf16, B [N,K] row-major bf16, D row-major (bf16 or fp32).
//   CTA tile 128x128x64, 8 warps (2m x 4n), warp tile 64x32, mma m16n8k16.
//   grid(N/128, M/128, batch), 256 threads, 3-stage cp.async pipeline.
// ---------------------------------------------------------------------------
__global__ void __launch_bounds__(256, 2)
gemm_bf16(const bf16* __restrict__ A, const bf16* __restrict__ B,
          void* __restrict__ Cv, const float* __restrict__ bias,
          const float* __restrict__ residual,
          int M, int N, int K, float scale,
          size_t sA, size_t sB, size_t sC, int outHalf) {
    extern __shared__ bf16 smh[];
    const uint32_t saddr = smem_u32(smh);
    const int tid = threadIdx.x;
    const int wid = tid >> 5, lid = tid & 31;
    const int gid = lid >> 2, tig = lid & 3;     // quad row / thread-in-group
    const int wm  = wid >> 2, wn  = wid & 3;     // warp grid 2x4

    const int row0 = blockIdx.y * BM;
    const int col0 = blockIdx.x * BN;
    const bf16* Ab = A + (size_t)blockIdx.z * sA + (size_t)row0 * K;
    const bf16* Bb = B + (size_t)blockIdx.z * sB + (size_t)col0 * K;

    float acc[4][4][4];
#pragma unroll
    for (int i = 0; i < 4; i++)
#pragma unroll
        for (int j = 0; j < 4; j++)
#pragma unroll
            for (int r = 0; r < 4; r++) acc[i][j][r] = 0.f;

    const int nch = K / BKH;

    auto load_stage = [&](int s, int kt) {
        uint32_t dA = saddr + (uint32_t)(s * STG_HALFS) * 2u;
        uint32_t dB = dA + (uint32_t)A_HALFS * 2u;
        const bf16* Ak = Ab + kt * BKH;
        const bf16* Bk = Bb + kt * BKH;
#pragma unroll
        for (int i = 0; i < 4; i++) {            // A: 128 rows x 8 x 16B
            int idx = tid + 256 * i;
            int r = idx >> 3, e = idx & 7;
            cpa16(dA + (uint32_t)(r * PITCH + e * 8) * 2u, Ak + (size_t)r * K + e * 8);
        }
#pragma unroll
        for (int i = 0; i < 4; i++) {            // B: 128 rows x 8 x 16B
            int idx = tid + 256 * i;
            int r = idx >> 3, e = idx & 7;
            cpa16(dB + (uint32_t)(r * PITCH + e * 8) * 2u, Bk + (size_t)r * K + e * 8);
        }
        asm volatile("cp.async.commit_group;" ::: "memory");
    };

    // prologue (nch >= 8 for all our shapes)
    load_stage(0, 0);
    load_stage(1, 1);

    for (int kt = 0; kt < nch; kt++) {
        int s = kt % NST;
        if (kt == nch - 1) asm volatile("cp.async.wait_group 0;" ::: "memory");
        else               asm volatile("cp.async.wait_group 1;" ::: "memory");
        __syncthreads();
        // overlap: fill stage (kt+2)%NST == (kt-1)%NST, fully consumed pre-barrier
        if (kt + 2 < nch) load_stage((kt + 2) % NST, kt + 2);

        const uint32_t* As = (const uint32_t*)(smh + s * STG_HALFS);
        const uint32_t* Bs = As + A_HALFS / 2;

#pragma unroll
        for (int ks = 0; ks < 4; ks++) {
            const int kw = ks * 8;               // u32 offset within 36-u32 row
            uint32_t a[4][4], b[4][2];
#pragma unroll
            for (int mt = 0; mt < 4; mt++) {
                int r = wm * 64 + mt * 16 + gid;
                a[mt][0] = As[r * 36 + kw + tig];
                a[mt][1] = As[(r + 8) * 36 + kw + tig];
                a[mt][2] = As[r * 36 + kw + tig + 4];
                a[mt][3] = As[(r + 8) * 36 + kw + tig + 4];
            }
#pragma unroll
            for (int nt = 0; nt < 4; nt++) {
                int n = wn * 32 + nt * 8 + gid;
                b[nt][0] = Bs[n * 36 + kw + tig];
                b[nt][1] = Bs[n * 36 + kw + tig + 4];
            }
#pragma unroll
            for (int mt = 0; mt < 4; mt++)
#pragma unroll
                for (int nt = 0; nt < 4; nt++)
                    asm volatile(
                        "mma.sync.aligned.m16n8k16.row.col.f32.bf16.bf16.f32 "
                        "{%0,%1,%2,%3}, {%4,%5,%6,%7}, {%8,%9}, {%0,%1,%2,%3};"
                        : "+f"(acc[mt][nt][0]), "+f"(acc[mt][nt][1]),
                          "+f"(acc[mt][nt][2]), "+f"(acc[mt][nt][3])
                        : "r"(a[mt][0]), "r"(a[mt][1]), "r"(a[mt][2]), "r"(a[mt][3]),
                          "r"(b[nt][0]), "r"(b[nt][1]));
        }
        __syncthreads();
    }

    // ---- epilogue ----
    if (outHalf) {
        bf16* Ch = (bf16*)Cv + (size_t)blockIdx.z * sC;
#pragma unroll
        for (int mt = 0; mt < 4; mt++) {
            int r = row0 + wm * 64 + mt * 16 + gid;
#pragma unroll
            for (int nt = 0; nt < 4; nt++) {
                int c = col0 + wn * 32 + nt * 8 + 2 * tig;
#pragma unroll
                for (int h = 0; h < 2; h++) {
                    int rr = r + h * 8;
                    float v0 = acc[mt][nt][2 * h + 0] * scale;
                    float v1 = acc[mt][nt][2 * h + 1] * scale;
                    if (bias) { v0 += bias[c]; v1 += bias[c + 1]; }
                    bf162 hv; hv.x = __float2bfloat16(v0); hv.y = __float2bfloat16(v1);
                    *(bf162*)(Ch + (size_t)rr * N + c) = hv;
                }
            }
        }
    } else {
        float* Cf = (float*)Cv + (size_t)blockIdx.z * sC;
        const float* Rb = residual ? residual + (size_t)blockIdx.z * sC : nullptr;
#pragma unroll
        for (int mt = 0; mt < 4; mt++) {
            int r = row0 + wm * 64 + mt * 16 + gid;
#pragma unroll
            for (int nt = 0; nt < 4; nt++) {
                int c = col0 + wn * 32 + nt * 8 + 2 * tig;
#pragma unroll
                for (int h = 0; h < 2; h++) {
                    int rr = r + h * 8;
                    float v0 = acc[mt][nt][2 * h + 0] * scale;
                    float v1 = acc[mt][nt][2 * h + 1] * scale;
                    if (bias) { v0 += bias[c]; v1 += bias[c + 1]; }
                    if (Rb) {
                        float2 rv = *(const float2*)(Rb + (size_t)rr * N + c);
                        v0 += rv.x; v1 += rv.y;
                    }
                    *(float2*)(Cf + (size_t)rr * N + c) = make_float2(v0, v1);
                }
            }
        }
    }
}

// ---------------------------------------------------------------------------
// Row softmax over bf16 logits, length 4096, in-place. fp32 math.
// ---------------------------------------------------------------------------
__global__ void softmax4096_h(bf16* __restrict__ S) {
    uint32_t* p = (uint32_t*)(S + (size_t)blockIdx.x * 4096);  // 2048 u32 pairs
    const int t = threadIdx.x;
    __shared__ float sh[8];

    float v[16];
#pragma unroll
    for (int i = 0; i < 8; i++) {
        uint32_t u = p[t + i * 256];
        bf162 h2 = *reinterpret_cast<bf162*>(&u);
        v[2 * i]     = __bfloat162float(h2.x);
        v[2 * i + 1] = __bfloat162float(h2.y);
    }
    float mx = -1e30f;
#pragma unroll
    for (int i = 0; i < 16; i++) mx = fmaxf(mx, v[i]);
#pragma unroll
    for (int off = 16; off > 0; off >>= 1)
        mx = fmaxf(mx, __shfl_xor_sync(0xffffffffu, mx, off));
    if ((t & 31) == 0) sh[t >> 5] = mx;
    __syncthreads();
    {
        float m = sh[t & 7];
#pragma unroll
        for (int off = 4; off > 0; off >>= 1)
            m = fmaxf(m, __shfl_xor_sync(0xffffffffu, m, off));
        mx = m;
    }
    __syncthreads();

    float s = 0.f;
#pragma unroll
    for (int i = 0; i < 16; i++) {
        v[i] = __expf(v[i] - mx);
        s += v[i];
    }
#pragma unroll
    for (int off = 16; off > 0; off >>= 1)
        s += __shfl_xor_sync(0xffffffffu, s, off);
    if ((t & 31) == 0) sh[t >> 5] = s;
    __syncthreads();
    {
        float m = sh[t & 7];
#pragma unroll
        for (int off = 4; off > 0; off >>= 1)
            m += __shfl_xor_sync(0xffffffffu, m, off);
        s = m;
    }
    float inv = 1.f / s;
#pragma unroll
    for (int i = 0; i < 8; i++) {
        bf162 h2;
        h2.x = __float2bfloat16(v[2 * i] * inv);
        h2.y = __float2bfloat16(v[2 * i + 1] * inv);
        p[t + i * 256] = *reinterpret_cast<uint32_t*>(&h2);
    }
}

// ---------------------------------------------------------------------------
// Launch
// ---------------------------------------------------------------------------
extern "C" void kernel_launch(void* const* d_in, const int* in_sizes, int n_in,
                              void* d_out, int out_size) {
    (void)in_sizes; (void)n_in; (void)out_size;

    const float* x     = (const float*)d_in[0];
    const float* gamma = (const float*)d_in[1];
    const float* beta  = (const float*)d_in[2];
    const float* wq    = (const float*)d_in[3];
    const float* bq    = (const float*)d_in[4];
    const float* wk    = (const float*)d_in[5];
    const float* bk    = (const float*)d_in[6];
    const float* wv    = (const float*)d_in[7];
    const float* bv    = (const float*)d_in[8];
    const float* wp    = (const float*)d_in[9];
    const float* bp    = (const float*)d_in[10];
    float* out = (float*)d_out;

    bf16 *xn, *q, *k, *v, *vt, *o, *wt, *attn;
    cudaGetSymbolAddress((void**)&xn,   h_xn);
    cudaGetSymbolAddress((void**)&q,    h_q);
    cudaGetSymbolAddress((void**)&k,    h_k);
    cudaGetSymbolAddress((void**)&v,    h_v);
    cudaGetSymbolAddress((void**)&vt,   h_vt);
    cudaGetSymbolAddress((void**)&o,    h_o);
    cudaGetSymbolAddress((void**)&wt,   h_wt);
    cudaGetSymbolAddress((void**)&attn, h_attn);

    cudaFuncSetAttribute(gemm_bf16, cudaFuncAttributeMaxDynamicSharedMemorySize, GEMM_SMEM);

    const float SCALE = 0.04419417382415922f;   // 1/sqrt(512)
    const size_t sQ = (size_t)4096 * 512;
    const size_t sS = (size_t)4096 * 4096;
    const size_t sW = (size_t)512 * 512;

    // GroupNorm -> bf16 xn
    gn_stats<<<64, 256>>>(x);
    gn_apply<<<4096, 256>>>(x, gamma, beta, xn);

    // Weight transposes (fp32 -> bf16, 512x512)
    dim3 tb(32, 8);
    transpose_f2h<<<dim3(16, 16, 1), tb>>>(wq, wt + 0 * sW, 512, 512);
    transpose_f2h<<<dim3(16, 16, 1), tb>>>(wk, wt + 1 * sW, 512, 512);
    transpose_f2h<<<dim3(16, 16, 1), tb>>>(wv, wt + 2 * sW, 512, 512);
    transpose_f2h<<<dim3(16, 16, 1), tb>>>(wp, wt + 3 * sW, 512, 512);

    // QKV: [8192,512] = xn @ w^T (NT), + bias -> bf16
    dim3 gQKV(512 / BN, 8192 / BM, 1);
    gemm_bf16<<<gQKV, 256, GEMM_SMEM>>>(xn, wt + 0 * sW, q, bq, nullptr, 8192, 512, 512, 1.f, 0, 0, 0, 1);
    gemm_bf16<<<gQKV, 256, GEMM_SMEM>>>(xn, wt + 1 * sW, k, bk, nullptr, 8192, 512, 512, 1.f, 0, 0, 0, 1);
    gemm_bf16<<<gQKV, 256, GEMM_SMEM>>>(xn, wt + 2 * sW, v, bv, nullptr, 8192, 512, 512, 1.f, 0, 0, 0, 1);

    // S = scale * Q @ K^T per batch -> bf16 logits
    dim3 gS(4096 / BN, 4096 / BM, 2);
    gemm_bf16<<<gS, 256, GEMM_SMEM>>>(q, k, attn, nullptr, nullptr, 4096, 4096, 512, SCALE, sQ, sQ, sS, 1);

    // softmax rows (bf16 in/out, fp32 math)
    softmax4096_h<<<8192, 256>>>(attn);

    // V^T per batch: [512,4096] bf16
    transpose_h<<<dim3(16, 128, 2), tb>>>(v, vt, 4096, 512, sQ, sQ);

    // O = P @ V = P @ (V^T)^T  (NT) -> bf16
    dim3 gPV(512 / BN, 4096 / BM, 2);
    gemm_bf16<<<gPV, 256, GEMM_SMEM>>>(attn, vt, o, nullptr, nullptr, 4096, 512, 4096, 1.f, sS, sQ, sQ, 1);

    // out = O @ wp^T (NT) + bp + x  -> fp32
    dim3 gP(512 / BN, 8192 / BM, 1);
    gemm_bf16<<<gP, 256, GEMM_SMEM>>>(o, wt + 3 * sW, out, bp, x, 8192, 512, 512, 1.f, 0, 0, 0, 0);
}

// round 15
// speedup vs baseline: 5.7814x; 1.0022x over previous
#include <cuda_runtime.h>
#include <cuda_bf16.h>
#include <cstdint>
#include <cstddef>

// ---------------------------------------------------------------------------
// AttentionBlock via mma.sync bf16 (m16n8k16 HMMA; tcgen05 PTX rejected: the
// harness PTX target is plain sm_103).
//   GroupNorm(32) -> QKV -> softmax(QK^T/sqrt(C)) V -> proj + residual
//   B=2, N_tok=4096, C=512.  fp32 I/O, bf16 GEMM operands, fp32 accum.
// All GEMMs are NT: D[m,n] = sum_k A[m,k]*B[n,k]; weights / V pre-transposed.
// ---------------------------------------------------------------------------

typedef unsigned long long u64;
typedef __nv_bfloat16  bf16;
typedef __nv_bfloat162 bf162;

// ---------------- GEMM tile config ----------------
#define BM 128
#define BN 128
#define BKH 64                       // bf16 elements per K-chunk (4 mma k-steps of 16)
#define NST 3                        // cp.async pipeline stages
#define PITCH 72                     // padded row pitch in bf16 elems (144 B)
#define A_HALFS (BM * PITCH)         // 9216
#define STG_HALFS (2 * A_HALFS)      // 18432 bf16 per stage (A + B)
#define GEMM_SMEM (NST * STG_HALFS * 2)   // 110592 bytes -> 2 CTA/SM

// ---------------- scratch (allocation-free) ----------------
__device__ bf16  h_xn [8192 * 512];
__device__ bf16  h_q  [8192 * 512];
__device__ bf16  h_k  [8192 * 512];
__device__ bf16  h_v  [8192 * 512];
__device__ bf16  h_vt [8192 * 512];                 // V^T per batch: [512,4096]
__device__ bf16  h_o  [8192 * 512];
__device__ bf16  h_wt [4 * 512 * 512];              // wq^T, wk^T, wv^T, wp^T (bf16)
__device__ bf16  h_attn[(size_t)2 * 4096 * 4096];
__device__ float g_mean[64];
__device__ float g_rstd[64];

// ---------------- helpers ----------------
__device__ __forceinline__ uint32_t smem_u32(const void* p) {
    uint32_t a;
    asm("{ .reg .u64 t; cvta.to.shared.u64 t, %1; cvt.u32.u64 %0, t; }" : "=r"(a) : "l"(p));
    return a;
}
__device__ __forceinline__ void cpa16(uint32_t dst, const void* src) {
    asm volatile("cp.async.cg.shared.global [%0], [%1], 16;" :: "r"(dst), "l"(src));
}

// ---------------------------------------------------------------------------
// GroupNorm
// ---------------------------------------------------------------------------
__global__ void gn_stats(const float* __restrict__ x) {
    int bg = blockIdx.x, b = bg >> 5, g = bg & 31;
    const float* base = x + (size_t)b * 4096 * 512 + g * 16;
    float s = 0.f, ss = 0.f;
    for (int i = threadIdx.x; i < 65536; i += 256) {
        int p = i >> 4, c = i & 15;
        float v = base[(size_t)p * 512 + c];
        s += v; ss += v * v;
    }
    __shared__ float sh1[256], sh2[256];
    sh1[threadIdx.x] = s; sh2[threadIdx.x] = ss;
    __syncthreads();
    for (int st = 128; st > 0; st >>= 1) {
        if (threadIdx.x < st) {
            sh1[threadIdx.x] += sh1[threadIdx.x + st];
            sh2[threadIdx.x] += sh2[threadIdx.x + st];
        }
        __syncthreads();
    }
    if (threadIdx.x == 0) {
        float m = sh1[0] * (1.f / 65536.f);
        float var = sh2[0] * (1.f / 65536.f) - m * m;
        g_mean[bg] = m;
        g_rstd[bg] = rsqrtf(var + 1e-5f);
    }
}

__global__ void gn_apply(const float* __restrict__ x,
                         const float* __restrict__ gamma,
                         const float* __restrict__ beta,
                         bf16* __restrict__ xn) {
    size_t e = ((size_t)blockIdx.x * blockDim.x + threadIdx.x) * 4;
    int c = (int)(e & 511);
    int b = (int)(e >> 21);
    int bg = b * 32 + (c >> 4);
    float m = g_mean[bg], r = g_rstd[bg];
    float4 xv = *(const float4*)(x + e);
    float o0 = (xv.x - m) * r * gamma[c + 0] + beta[c + 0];
    float o1 = (xv.y - m) * r * gamma[c + 1] + beta[c + 1];
    float o2 = (xv.z - m) * r * gamma[c + 2] + beta[c + 2];
    float o3 = (xv.w - m) * r * gamma[c + 3] + beta[c + 3];
    bf162 p0; p0.x = __float2bfloat16(o0); p0.y = __float2bfloat16(o1);
    bf162 p1; p1.x = __float2bfloat16(o2); p1.y = __float2bfloat16(o3);
    *(bf162*)(xn + e)     = p0;
    *(bf162*)(xn + e + 2) = p1;
}

// ---------------------------------------------------------------------------
// Transposes
// ---------------------------------------------------------------------------
// fp32 [R,C] -> bf16 [C,R]   (weights, 512x512)
__global__ void transpose_f2h(const float* __restrict__ in, bf16* __restrict__ out,
                              int R, int C) {
    __shared__ float t[32][33];
    int c0 = blockIdx.x * 32, r0 = blockIdx.y * 32;
    int tx = threadIdx.x, ty = threadIdx.y;
#pragma unroll
    for (int i = 0; i < 32; i += 8)
        t[ty + i][tx] = in[(size_t)(r0 + ty + i) * C + c0 + tx];
    __syncthreads();
#pragma unroll
    for (int i = 0; i < 32; i += 8)
        out[(size_t)(c0 + ty + i) * R + r0 + tx] = __float2bfloat16(t[tx][ty + i]);
}

// bf16 [R,C] -> bf16 [C,R] per batch (V^T)
__global__ void transpose_h(const bf16* __restrict__ in, bf16* __restrict__ out,
                            int R, int C, size_t sIn, size_t sOut) {
    in  += (size_t)blockIdx.z * sIn;
    out += (size_t)blockIdx.z * sOut;
    __shared__ bf16 t[32][34];
    int c0 = blockIdx.x * 32, r0 = blockIdx.y * 32;
    int tx = threadIdx.x, ty = threadIdx.y;
#pragma unroll
    for (int i = 0; i < 32; i += 8)
        t[ty + i][tx] = in[(size_t)(r0 + ty + i) * C + c0 + tx];
    __syncthreads();
#pragma unroll
    for (int i = 0; i < 32; i += 8)
        out[(size_t)(c0 + ty + i) * R + r0 + tx] = t[tx][ty + i];
}

// ---------------------------------------------------------------------------
// bf16 mma.sync GEMM (NT): D = scale*(A @ B^T) [+ bias] [+ residual]
//   A [M,K] row-major bf16, B [N,K] row-major bf16, D row-major (bf16 or fp32).
//   CTA tile 128x128x64, 8 warps (2m x 4n), warp tile 64x32, mma m16n8k16.
//   grid(N/128, M/128, batch), 256 threads, 3-stage cp.async pipeline.
// ---------------------------------------------------------------------------
__global__ void __launch_bounds__(256, 2)
gemm_bf16(const bf16* __restrict__ A, const bf16* __restrict__ B,
          void* __restrict__ Cv, const float* __restrict__ bias,
          const float* __restrict__ residual,
          int M, int N, int K, float scale,
          size_t sA, size_t sB, size_t sC, int outHalf) {
    extern __shared__ bf16 smh[];
    const uint32_t saddr = smem_u32(smh);
    const int tid = threadIdx.x;
    const int wid = tid >> 5, lid = tid & 31;
    const int gid = lid >> 2, tig = lid & 3;     // quad row / thread-in-group
    const int wm  = wid >> 2, wn  = wid & 3;     // warp grid 2x4

    const int row0 = blockIdx.y * BM;
    const int col0 = blockIdx.x * BN;
    const bf16* Ab = A + (size_t)blockIdx.z * sA + (size_t)row0 * K;
    const bf16* Bb = B + (size_t)blockIdx.z * sB + (size_t)col0 * K;

    float acc[4][4][4];
#pragma unroll
    for (int i = 0; i < 4; i++)
#pragma unroll
        for (int j = 0; j < 4; j++)
#pragma unroll
            for (int r = 0; r < 4; r++) acc[i][j][r] = 0.f;

    const int nch = K / BKH;

    auto load_stage = [&](int s, int kt) {
        uint32_t dA = saddr + (uint32_t)(s * STG_HALFS) * 2u;
        uint32_t dB = dA + (uint32_t)A_HALFS * 2u;
        const bf16* Ak = Ab + kt * BKH;
        const bf16* Bk = Bb + kt * BKH;
#pragma unroll
        for (int i = 0; i < 4; i++) {            // A: 128 rows x 8 x 16B
            int idx = tid + 256 * i;
            int r = idx >> 3, e = idx & 7;
            cpa16(dA + (uint32_t)(r * PITCH + e * 8) * 2u, Ak + (size_t)r * K + e * 8);
        }
#pragma unroll
        for (int i = 0; i < 4; i++) {            // B: 128 rows x 8 x 16B
            int idx = tid + 256 * i;
            int r = idx >> 3, e = idx & 7;
            cpa16(dB + (uint32_t)(r * PITCH + e * 8) * 2u, Bk + (size_t)r * K + e * 8);
        }
        asm volatile("cp.async.commit_group;" ::: "memory");
    };

    // prologue (nch >= 8 for all our shapes)
    load_stage(0, 0);
    load_stage(1, 1);

    for (int kt = 0; kt < nch; kt++) {
        int s = kt % NST;
        if (kt == nch - 1) asm volatile("cp.async.wait_group 0;" ::: "memory");
        else               asm volatile("cp.async.wait_group 1;" ::: "memory");
        __syncthreads();
        // overlap: fill stage (kt+2)%NST == (kt-1)%NST, fully consumed pre-barrier
        if (kt + 2 < nch) load_stage((kt + 2) % NST, kt + 2);

        const uint32_t* As = (const uint32_t*)(smh + s * STG_HALFS);
        const uint32_t* Bs = As + A_HALFS / 2;

#pragma unroll
        for (int ks = 0; ks < 4; ks++) {
            const int kw = ks * 8;               // u32 offset within 36-u32 row
            uint32_t a[4][4], b[4][2];
#pragma unroll
            for (int mt = 0; mt < 4; mt++) {
                int r = wm * 64 + mt * 16 + gid;
                a[mt][0] = As[r * 36 + kw + tig];
                a[mt][1] = As[(r + 8) * 36 + kw + tig];
                a[mt][2] = As[r * 36 + kw + tig + 4];
                a[mt][3] = As[(r + 8) * 36 + kw + tig + 4];
            }
#pragma unroll
            for (int nt = 0; nt < 4; nt++) {
                int n = wn * 32 + nt * 8 + gid;
                b[nt][0] = Bs[n * 36 + kw + tig];
                b[nt][1] = Bs[n * 36 + kw + tig + 4];
            }
#pragma unroll
            for (int mt = 0; mt < 4; mt++)
#pragma unroll
                for (int nt = 0; nt < 4; nt++)
                    asm volatile(
                        "mma.sync.aligned.m16n8k16.row.col.f32.bf16.bf16.f32 "
                        "{%0,%1,%2,%3}, {%4,%5,%6,%7}, {%8,%9}, {%0,%1,%2,%3};"
                        : "+f"(acc[mt][nt][0]), "+f"(acc[mt][nt][1]),
                          "+f"(acc[mt][nt][2]), "+f"(acc[mt][nt][3])
                        : "r"(a[mt][0]), "r"(a[mt][1]), "r"(a[mt][2]), "r"(a[mt][3]),
                          "r"(b[nt][0]), "r"(b[nt][1]));
        }
        __syncthreads();
    }

    // ---- epilogue ----
    if (outHalf) {
        bf16* Ch = (bf16*)Cv + (size_t)blockIdx.z * sC;
#pragma unroll
        for (int mt = 0; mt < 4; mt++) {
            int r = row0 + wm * 64 + mt * 16 + gid;
#pragma unroll
            for (int nt = 0; nt < 4; nt++) {
                int c = col0 + wn * 32 + nt * 8 + 2 * tig;
#pragma unroll
                for (int h = 0; h < 2; h++) {
                    int rr = r + h * 8;
                    float v0 = acc[mt][nt][2 * h + 0] * scale;
                    float v1 = acc[mt][nt][2 * h + 1] * scale;
                    if (bias) { v0 += bias[c]; v1 += bias[c + 1]; }
                    bf162 hv; hv.x = __float2bfloat16(v0); hv.y = __float2bfloat16(v1);
                    *(bf162*)(Ch + (size_t)rr * N + c) = hv;
                }
            }
        }
    } else {
        float* Cf = (float*)Cv + (size_t)blockIdx.z * sC;
        const float* Rb = residual ? residual + (size_t)blockIdx.z * sC : nullptr;
#pragma unroll
        for (int mt = 0; mt < 4; mt++) {
            int r = row0 + wm * 64 + mt * 16 + gid;
#pragma unroll
            for (int nt = 0; nt < 4; nt++) {
                int c = col0 + wn * 32 + nt * 8 + 2 * tig;
#pragma unroll
                for (int h = 0; h < 2; h++) {
                    int rr = r + h * 8;
                    float v0 = acc[mt][nt][2 * h + 0] * scale;
                    float v1 = acc[mt][nt][2 * h + 1] * scale;
                    if (bias) { v0 += bias[c]; v1 += bias[c + 1]; }
                    if (Rb) {
                        float2 rv = *(const float2*)(Rb + (size_t)rr * N + c);
                        v0 += rv.x; v1 += rv.y;
                    }
                    *(float2*)(Cf + (size_t)rr * N + c) = make_float2(v0, v1);
                }
            }
        }
    }
}

// ---------------------------------------------------------------------------
// Row softmax over bf16 logits, length 4096, in-place. fp32 math.
// ---------------------------------------------------------------------------
__global__ void softmax4096_h(bf16* __restrict__ S) {
    uint32_t* p = (uint32_t*)(S + (size_t)blockIdx.x * 4096);  // 2048 u32 pairs
    const int t = threadIdx.x;
    __shared__ float sh[8];

    float v[16];
#pragma unroll
    for (int i = 0; i < 8; i++) {
        uint32_t u = p[t + i * 256];
        bf162 h2 = *reinterpret_cast<bf162*>(&u);
        v[2 * i]     = __bfloat162float(h2.x);
        v[2 * i + 1] = __bfloat162float(h2.y);
    }
    float mx = -1e30f;
#pragma unroll
    for (int i = 0; i < 16; i++) mx = fmaxf(mx, v[i]);
#pragma unroll
    for (int off = 16; off > 0; off >>= 1)
        mx = fmaxf(mx, __shfl_xor_sync(0xffffffffu, mx, off));
    if ((t & 31) == 0) sh[t >> 5] = mx;
    __syncthreads();
    {
        float m = sh[t & 7];
#pragma unroll
        for (int off = 4; off > 0; off >>= 1)
            m = fmaxf(m, __shfl_xor_sync(0xffffffffu, m, off));
        mx = m;
    }
    __syncthreads();

    float s = 0.f;
#pragma unroll
    for (int i = 0; i < 16; i++) {
        v[i] = __expf(v[i] - mx);
        s += v[i];
    }
#pragma unroll
    for (int off = 16; off > 0; off >>= 1)
        s += __shfl_xor_sync(0xffffffffu, s, off);
    if ((t & 31) == 0) sh[t >> 5] = s;
    __syncthreads();
    {
        float m = sh[t & 7];
#pragma unroll
        for (int off = 4; off > 0; off >>= 1)
            m += __shfl_xor_sync(0xffffffffu, m, off);
        s = m;
    }
    float inv = 1.f / s;
#pragma unroll
    for (int i = 0; i < 8; i++) {
        bf162 h2;
        h2.x = __float2bfloat16(v[2 * i] * inv);
        h2.y = __float2bfloat16(v[2 * i + 1] * inv);
        p[t + i * 256] = *reinterpret_cast<uint32_t*>(&h2);
    }
}

// ---------------------------------------------------------------------------
// Launch
// ---------------------------------------------------------------------------
extern "C" void kernel_launch(void* const* d_in, const int* in_sizes, int n_in,
                              void* d_out, int out_size) {
    (void)in_sizes; (void)n_in; (void)out_size;

    const float* x     = (const float*)d_in[0];
    const float* gamma = (const float*)d_in[1];
    const float* beta  = (const float*)d_in[2];
    const float* wq    = (const float*)d_in[3];
    const float* bq    = (const float*)d_in[4];
    const float* wk    = (const float*)d_in[5];
    const float* bk    = (const float*)d_in[6];
    const float* wv    = (const float*)d_in[7];
    const float* bv    = (const float*)d_in[8];
    const float* wp    = (const float*)d_in[9];
    const float* bp    = (const float*)d_in[10];
    float* out = (float*)d_out;

    bf16 *xn, *q, *k, *v, *vt, *o, *wt, *attn;
    cudaGetSymbolAddress((void**)&xn,   h_xn);
    cudaGetSymbolAddress((void**)&q,    h_q);
    cudaGetSymbolAddress((void**)&k,    h_k);
    cudaGetSymbolAddress((void**)&v,    h_v);
    cudaGetSymbolAddress((void**)&vt,   h_vt);
    cudaGetSymbolAddress((void**)&o,    h_o);
    cudaGetSymbolAddress((void**)&wt,   h_wt);
    cudaGetSymbolAddress((void**)&attn, h_attn);

    cudaFuncSetAttribute(gemm_bf16, cudaFuncAttributeMaxDynamicSharedMemorySize, GEMM_SMEM);

    const float SCALE = 0.04419417382415922f;   // 1/sqrt(512)
    const size_t sQ = (size_t)4096 * 512;
    const size_t sS = (size_t)4096 * 4096;
    const size_t sW = (size_t)512 * 512;

    // GroupNorm -> bf16 xn
    gn_stats<<<64, 256>>>(x);
    gn_apply<<<4096, 256>>>(x, gamma, beta, xn);

    // Weight transposes (fp32 -> bf16, 512x512)
    dim3 tb(32, 8);
    transpose_f2h<<<dim3(16, 16, 1), tb>>>(wq, wt + 0 * sW, 512, 512);
    transpose_f2h<<<dim3(16, 16, 1), tb>>>(wk, wt + 1 * sW, 512, 512);
    transpose_f2h<<<dim3(16, 16, 1), tb>>>(wv, wt + 2 * sW, 512, 512);
    transpose_f2h<<<dim3(16, 16, 1), tb>>>(wp, wt + 3 * sW, 512, 512);

    // QKV: [8192,512] = xn @ w^T (NT), + bias -> bf16
    dim3 gQKV(512 / BN, 8192 / BM, 1);
    gemm_bf16<<<gQKV, 256, GEMM_SMEM>>>(xn, wt + 0 * sW, q, bq, nullptr, 8192, 512, 512, 1.f, 0, 0, 0, 1);
    gemm_bf16<<<gQKV, 256, GEMM_SMEM>>>(xn, wt + 1 * sW, k, bk, nullptr, 8192, 512, 512, 1.f, 0, 0, 0, 1);
    gemm_bf16<<<gQKV, 256, GEMM_SMEM>>>(xn, wt + 2 * sW, v, bv, nullptr, 8192, 512, 512, 1.f, 0, 0, 0, 1);

    // S = scale * Q @ K^T per batch -> bf16 logits
    dim3 gS(4096 / BN, 4096 / BM, 2);
    gemm_bf16<<<gS, 256, GEMM_SMEM>>>(q, k, attn, nullptr, nullptr, 4096, 4096, 512, SCALE, sQ, sQ, sS, 1);

    // softmax rows (bf16 in/out, fp32 math)
    softmax4096_h<<<8192, 256>>>(attn);

    // V^T per batch: [512,4096] bf16
    transpose_h<<<dim3(16, 128, 2), tb>>>(v, vt, 4096, 512, sQ, sQ);

    // O = P @ V = P @ (V^T)^T  (NT) -> bf16
    dim3 gPV(512 / BN, 4096 / BM, 2);
    gemm_bf16<<<gPV, 256, GEMM_SMEM>>>(attn, vt, o, nullptr, nullptr, 4096, 512, 4096, 1.f, sS, sQ, sQ, 1);

    // out = O @ wp^T (NT) + bp + x  -> fp32
    dim3 gP(512 / BN, 8192 / BM, 1);
    gemm_bf16<<<gP, 256, GEMM_SMEM>>>(o, wt + 3 * sW, out, bp, x, 8192, 512, 512, 1.f, 0, 0, 0, 0);
}

// round 16
// speedup vs baseline: 6.2938x; 1.0886x over previous
#include <cuda_runtime.h>
#include <cuda_bf16.h>
#include <cstdint>
#include <cstddef>

// ---------------------------------------------------------------------------
// AttentionBlock via mma.sync bf16 m16n8k16 + ldmatrix operand feed.
//   GroupNorm(32) -> QKV -> softmax(QK^T/sqrt(C)) V -> proj + residual
//   B=2, N_tok=4096, C=512.  fp32 I/O, bf16 GEMM operands, fp32 accum.
// All GEMMs NT: D[m,n] = sum_k A[m,k]*B[n,k]; weights / V pre-transposed.
// ---------------------------------------------------------------------------

typedef __nv_bfloat16  bf16;
typedef __nv_bfloat162 bf162;

// ---------------- GEMM tile config ----------------
#define BM 128
#define BN 128
#define BKH 64                       // bf16 elements per K-chunk (4 mma k-steps of 16)
#define NST 3                        // cp.async pipeline stages
#define PITCH 72                     // padded row pitch in bf16 elems (144 B)
#define A_HALFS (BM * PITCH)         // 9216
#define STG_HALFS (2 * A_HALFS)      // 18432 bf16 per stage (A + B)
#define GEMM_SMEM (NST * STG_HALFS * 2)   // 110592 bytes -> 2 CTA/SM

// ---------------- scratch (allocation-free) ----------------
__device__ bf16  h_xn [8192 * 512];
__device__ bf16  h_q  [8192 * 512];
__device__ bf16  h_k  [8192 * 512];
__device__ bf16  h_v  [8192 * 512];
__device__ bf16  h_vt [8192 * 512];                 // V^T per batch: [512,4096]
__device__ bf16  h_o  [8192 * 512];
__device__ bf16  h_wt [4 * 512 * 512];              // wq^T, wk^T, wv^T, wp^T (bf16)
__device__ bf16  h_attn[(size_t)2 * 4096 * 4096];
__device__ float g_mean[64];
__device__ float g_rstd[64];

// ---------------- helpers ----------------
__device__ __forceinline__ uint32_t smem_u32(const void* p) {
    uint32_t a;
    asm("{ .reg .u64 t; cvta.to.shared.u64 t, %1; cvt.u32.u64 %0, t; }" : "=r"(a) : "l"(p));
    return a;
}
__device__ __forceinline__ void cpa16(uint32_t dst, const void* src) {
    asm volatile("cp.async.cg.shared.global [%0], [%1], 16;" :: "r"(dst), "l"(src));
}
#define LDSM_X4(r, addr) \
    asm volatile("ldmatrix.sync.aligned.m8n8.x4.shared.b16 {%0,%1,%2,%3}, [%4];" \
        : "=r"((r)[0]), "=r"((r)[1]), "=r"((r)[2]), "=r"((r)[3]) : "r"(addr))

// ---------------------------------------------------------------------------
// GroupNorm
// ---------------------------------------------------------------------------
__global__ void gn_stats(const float* __restrict__ x) {
    int bg = blockIdx.x, b = bg >> 5, g = bg & 31;
    const float* base = x + (size_t)b * 4096 * 512 + g * 16;
    float s = 0.f, ss = 0.f;
    for (int i = threadIdx.x; i < 65536; i += 256) {
        int p = i >> 4, c = i & 15;
        float v = base[(size_t)p * 512 + c];
        s += v; ss += v * v;
    }
    __shared__ float sh1[256], sh2[256];
    sh1[threadIdx.x] = s; sh2[threadIdx.x] = ss;
    __syncthreads();
    for (int st = 128; st > 0; st >>= 1) {
        if (threadIdx.x < st) {
            sh1[threadIdx.x] += sh1[threadIdx.x + st];
            sh2[threadIdx.x] += sh2[threadIdx.x + st];
        }
        __syncthreads();
    }
    if (threadIdx.x == 0) {
        float m = sh1[0] * (1.f / 65536.f);
        float var = sh2[0] * (1.f / 65536.f) - m * m;
        g_mean[bg] = m;
        g_rstd[bg] = rsqrtf(var + 1e-5f);
    }
}

__global__ void gn_apply(const float* __restrict__ x,
                         const float* __restrict__ gamma,
                         const float* __restrict__ beta,
                         bf16* __restrict__ xn) {
    size_t e = ((size_t)blockIdx.x * blockDim.x + threadIdx.x) * 4;
    int c = (int)(e & 511);
    int b = (int)(e >> 21);
    int bg = b * 32 + (c >> 4);
    float m = g_mean[bg], r = g_rstd[bg];
    float4 xv = *(const float4*)(x + e);
    float o0 = (xv.x - m) * r * gamma[c + 0] + beta[c + 0];
    float o1 = (xv.y - m) * r * gamma[c + 1] + beta[c + 1];
    float o2 = (xv.z - m) * r * gamma[c + 2] + beta[c + 2];
    float o3 = (xv.w - m) * r * gamma[c + 3] + beta[c + 3];
    bf162 p0; p0.x = __float2bfloat16(o0); p0.y = __float2bfloat16(o1);
    bf162 p1; p1.x = __float2bfloat16(o2); p1.y = __float2bfloat16(o3);
    *(bf162*)(xn + e)     = p0;
    *(bf162*)(xn + e + 2) = p1;
}

// ---------------------------------------------------------------------------
// Transposes
// ---------------------------------------------------------------------------
__global__ void transpose_f2h(const float* __restrict__ in, bf16* __restrict__ out,
                              int R, int C) {
    __shared__ float t[32][33];
    int c0 = blockIdx.x * 32, r0 = blockIdx.y * 32;
    int tx = threadIdx.x, ty = threadIdx.y;
#pragma unroll
    for (int i = 0; i < 32; i += 8)
        t[ty + i][tx] = in[(size_t)(r0 + ty + i) * C + c0 + tx];
    __syncthreads();
#pragma unroll
    for (int i = 0; i < 32; i += 8)
        out[(size_t)(c0 + ty + i) * R + r0 + tx] = __float2bfloat16(t[tx][ty + i]);
}

__global__ void transpose_h(const bf16* __restrict__ in, bf16* __restrict__ out,
                            int R, int C, size_t sIn, size_t sOut) {
    in  += (size_t)blockIdx.z * sIn;
    out += (size_t)blockIdx.z * sOut;
    __shared__ bf16 t[32][34];
    int c0 = blockIdx.x * 32, r0 = blockIdx.y * 32;
    int tx = threadIdx.x, ty = threadIdx.y;
#pragma unroll
    for (int i = 0; i < 32; i += 8)
        t[ty + i][tx] = in[(size_t)(r0 + ty + i) * C + c0 + tx];
    __syncthreads();
#pragma unroll
    for (int i = 0; i < 32; i += 8)
        out[(size_t)(c0 + ty + i) * R + r0 + tx] = t[tx][ty + i];
}

// ---------------------------------------------------------------------------
// bf16 mma.sync GEMM (NT): D = scale*(A @ B^T) [+ bias] [+ residual]
//   CTA tile 128x128x64, 8 warps (2m x 4n), warp tile 64x32, mma m16n8k16.
//   ldmatrix.x4 operand feed; 3-stage cp.async pipeline; 256 threads.
// ---------------------------------------------------------------------------
__global__ void __launch_bounds__(256, 2)
gemm_bf16(const bf16* __restrict__ A, const bf16* __restrict__ B,
          void* __restrict__ Cv, const float* __restrict__ bias,
          const float* __restrict__ residual,
          int M, int N, int K, float scale,
          size_t sA, size_t sB, size_t sC, int outHalf) {
    extern __shared__ bf16 smh[];
    const uint32_t saddr = smem_u32(smh);
    const int tid = threadIdx.x;
    const int wid = tid >> 5, lid = tid & 31;
    const int gid = lid >> 2, tig = lid & 3;     // quad row / thread-in-group
    const int wm  = wid >> 2, wn  = wid & 3;     // warp grid 2x4

    const int row0 = blockIdx.y * BM;
    const int col0 = blockIdx.x * BN;
    const bf16* Ab = A + (size_t)blockIdx.z * sA + (size_t)row0 * K;
    const bf16* Bb = B + (size_t)blockIdx.z * sB + (size_t)col0 * K;

    // ldmatrix per-lane source offsets (bytes, within stage)
    // A x4: mat0=(m0-7,k0-7) mat1=(m8-15,k0-7) mat2=(m0-7,k8-15) mat3=(m8-15,k8-15)
    const int lAr = (lid & 7) + ((lid >> 3) & 1) * 8;
    const int lAc = (lid >> 4) * 8;
    // B x4: mat0=(n0-7,k0-7) mat1=(n0-7,k8-15) mat2=(n8-15,k0-7) mat3=(n8-15,k8-15)
    const int lBr = (lid & 7) + (lid >> 4) * 8;
    const int lBc = ((lid >> 3) & 1) * 8;
    const uint32_t aOff = saddr + 2u * (uint32_t)((wm * 64 + lAr) * PITCH + lAc);
    const uint32_t bOff = saddr + 2u * (uint32_t)(A_HALFS + (wn * 32 + lBr) * PITCH + lBc);

    float acc[4][4][4];
#pragma unroll
    for (int i = 0; i < 4; i++)
#pragma unroll
        for (int j = 0; j < 4; j++)
#pragma unroll
            for (int r = 0; r < 4; r++) acc[i][j][r] = 0.f;

    const int nch = K / BKH;

    auto load_stage = [&](int s, int kt) {
        uint32_t dA = saddr + (uint32_t)(s * STG_HALFS) * 2u;
        uint32_t dB = dA + (uint32_t)A_HALFS * 2u;
        const bf16* Ak = Ab + kt * BKH;
        const bf16* Bk = Bb + kt * BKH;
#pragma unroll
        for (int i = 0; i < 4; i++) {            // A: 128 rows x 8 x 16B
            int idx = tid + 256 * i;
            int r = idx >> 3, e = idx & 7;
            cpa16(dA + (uint32_t)(r * PITCH + e * 8) * 2u, Ak + (size_t)r * K + e * 8);
        }
#pragma unroll
        for (int i = 0; i < 4; i++) {            // B: 128 rows x 8 x 16B
            int idx = tid + 256 * i;
            int r = idx >> 3, e = idx & 7;
            cpa16(dB + (uint32_t)(r * PITCH + e * 8) * 2u, Bk + (size_t)r * K + e * 8);
        }
        asm volatile("cp.async.commit_group;" ::: "memory");
    };

    load_stage(0, 0);
    load_stage(1, 1);

    for (int kt = 0; kt < nch; kt++) {
        int s = kt % NST;
        if (kt == nch - 1) asm volatile("cp.async.wait_group 0;" ::: "memory");
        else               asm volatile("cp.async.wait_group 1;" ::: "memory");
        __syncthreads();
        if (kt + 2 < nch) load_stage((kt + 2) % NST, kt + 2);

        const uint32_t stB = (uint32_t)(s * STG_HALFS) * 2u;

#pragma unroll
        for (int ks = 0; ks < 4; ks++) {
            uint32_t a[4][4], b[2][4];
#pragma unroll
            for (int mt = 0; mt < 4; mt++)       // 16 m-rows per mt
                LDSM_X4(a[mt], aOff + stB + (uint32_t)(mt * 16 * PITCH + ks * 16) * 2u);
#pragma unroll
            for (int p = 0; p < 2; p++)          // 16 n-rows per p (nt pair)
                LDSM_X4(b[p], bOff + stB + (uint32_t)(p * 16 * PITCH + ks * 16) * 2u);

#pragma unroll
            for (int mt = 0; mt < 4; mt++)
#pragma unroll
                for (int nt = 0; nt < 4; nt++)
                    asm volatile(
                        "mma.sync.aligned.m16n8k16.row.col.f32.bf16.bf16.f32 "
                        "{%0,%1,%2,%3}, {%4,%5,%6,%7}, {%8,%9}, {%0,%1,%2,%3};"
                        : "+f"(acc[mt][nt][0]), "+f"(acc[mt][nt][1]),
                          "+f"(acc[mt][nt][2]), "+f"(acc[mt][nt][3])
                        : "r"(a[mt][0]), "r"(a[mt][1]), "r"(a[mt][2]), "r"(a[mt][3]),
                          "r"(b[nt >> 1][(nt & 1) * 2]), "r"(b[nt >> 1][(nt & 1) * 2 + 1]));
        }
        // no trailing barrier: next iteration's top barrier (post wait_group)
        // orders this chunk's LDSM reads before any cp.async overwrite.
    }

    // ---- epilogue ----
    if (outHalf) {
        bf16* Ch = (bf16*)Cv + (size_t)blockIdx.z * sC;
#pragma unroll
        for (int mt = 0; mt < 4; mt++) {
            int r = row0 + wm * 64 + mt * 16 + gid;
#pragma unroll
            for (int nt = 0; nt < 4; nt++) {
                int c = col0 + wn * 32 + nt * 8 + 2 * tig;
#pragma unroll
                for (int h = 0; h < 2; h++) {
                    int rr = r + h * 8;
                    float v0 = acc[mt][nt][2 * h + 0] * scale;
                    float v1 = acc[mt][nt][2 * h + 1] * scale;
                    if (bias) { v0 += bias[c]; v1 += bias[c + 1]; }
                    bf162 hv; hv.x = __float2bfloat16(v0); hv.y = __float2bfloat16(v1);
                    *(bf162*)(Ch + (size_t)rr * N + c) = hv;
                }
            }
        }
    } else {
        float* Cf = (float*)Cv + (size_t)blockIdx.z * sC;
        const float* Rb = residual ? residual + (size_t)blockIdx.z * sC : nullptr;
#pragma unroll
        for (int mt = 0; mt < 4; mt++) {
            int r = row0 + wm * 64 + mt * 16 + gid;
#pragma unroll
            for (int nt = 0; nt < 4; nt++) {
                int c = col0 + wn * 32 + nt * 8 + 2 * tig;
#pragma unroll
                for (int h = 0; h < 2; h++) {
                    int rr = r + h * 8;
                    float v0 = acc[mt][nt][2 * h + 0] * scale;
                    float v1 = acc[mt][nt][2 * h + 1] * scale;
                    if (bias) { v0 += bias[c]; v1 += bias[c + 1]; }
                    if (Rb) {
                        float2 rv = *(const float2*)(Rb + (size_t)rr * N + c);
                        v0 += rv.x; v1 += rv.y;
                    }
                    *(float2*)(Cf + (size_t)rr * N + c) = make_float2(v0, v1);
                }
            }
        }
    }
}

// ---------------------------------------------------------------------------
// Row softmax over bf16 logits, length 4096, in-place. fp32 math.
// ---------------------------------------------------------------------------
__global__ void softmax4096_h(bf16* __restrict__ S) {
    uint32_t* p = (uint32_t*)(S + (size_t)blockIdx.x * 4096);
    const int t = threadIdx.x;
    __shared__ float sh[8];

    float v[16];
#pragma unroll
    for (int i = 0; i < 8; i++) {
        uint32_t u = p[t + i * 256];
        bf162 h2 = *reinterpret_cast<bf162*>(&u);
        v[2 * i]     = __bfloat162float(h2.x);
        v[2 * i + 1] = __bfloat162float(h2.y);
    }
    float mx = -1e30f;
#pragma unroll
    for (int i = 0; i < 16; i++) mx = fmaxf(mx, v[i]);
#pragma unroll
    for (int off = 16; off > 0; off >>= 1)
        mx = fmaxf(mx, __shfl_xor_sync(0xffffffffu, mx, off));
    if ((t & 31) == 0) sh[t >> 5] = mx;
    __syncthreads();
    {
        float m = sh[t & 7];
#pragma unroll
        for (int off = 4; off > 0; off >>= 1)
            m = fmaxf(m, __shfl_xor_sync(0xffffffffu, m, off));
        mx = m;
    }
    __syncthreads();

    float s = 0.f;
#pragma unroll
    for (int i = 0; i < 16; i++) {
        v[i] = __expf(v[i] - mx);
        s += v[i];
    }
#pragma unroll
    for (int off = 16; off > 0; off >>= 1)
        s += __shfl_xor_sync(0xffffffffu, s, off);
    if ((t & 31) == 0) sh[t >> 5] = s;
    __syncthreads();
    {
        float m = sh[t & 7];
#pragma unroll
        for (int off = 4; off > 0; off >>= 1)
            m += __shfl_xor_sync(0xffffffffu, m, off);
        s = m;
    }
    float inv = 1.f / s;
#pragma unroll
    for (int i = 0; i < 8; i++) {
        bf162 h2;
        h2.x = __float2bfloat16(v[2 * i] * inv);
        h2.y = __float2bfloat16(v[2 * i + 1] * inv);
        p[t + i * 256] = *reinterpret_cast<uint32_t*>(&h2);
    }
}

// ---------------------------------------------------------------------------
// Launch
// ---------------------------------------------------------------------------
extern "C" void kernel_launch(void* const* d_in, const int* in_sizes, int n_in,
                              void* d_out, int out_size) {
    (void)in_sizes; (void)n_in; (void)out_size;

    const float* x     = (const float*)d_in[0];
    const float* gamma = (const float*)d_in[1];
    const float* beta  = (const float*)d_in[2];
    const float* wq    = (const float*)d_in[3];
    const float* bq    = (const float*)d_in[4];
    const float* wk    = (const float*)d_in[5];
    const float* bk    = (const float*)d_in[6];
    const float* wv    = (const float*)d_in[7];
    const float* bv    = (const float*)d_in[8];
    const float* wp    = (const float*)d_in[9];
    const float* bp    = (const float*)d_in[10];
    float* out = (float*)d_out;

    bf16 *xn, *q, *k, *v, *vt, *o, *wt, *attn;
    cudaGetSymbolAddress((void**)&xn,   h_xn);
    cudaGetSymbolAddress((void**)&q,    h_q);
    cudaGetSymbolAddress((void**)&k,    h_k);
    cudaGetSymbolAddress((void**)&v,    h_v);
    cudaGetSymbolAddress((void**)&vt,   h_vt);
    cudaGetSymbolAddress((void**)&o,    h_o);
    cudaGetSymbolAddress((void**)&wt,   h_wt);
    cudaGetSymbolAddress((void**)&attn, h_attn);

    cudaFuncSetAttribute(gemm_bf16, cudaFuncAttributeMaxDynamicSharedMemorySize, GEMM_SMEM);

    const float SCALE = 0.04419417382415922f;   // 1/sqrt(512)
    const size_t sQ = (size_t)4096 * 512;
    const size_t sS = (size_t)4096 * 4096;
    const size_t sW = (size_t)512 * 512;

    // GroupNorm -> bf16 xn
    gn_stats<<<64, 256>>>(x);
    gn_apply<<<4096, 256>>>(x, gamma, beta, xn);

    // Weight transposes (fp32 -> bf16, 512x512)
    dim3 tb(32, 8);
    transpose_f2h<<<dim3(16, 16, 1), tb>>>(wq, wt + 0 * sW, 512, 512);
    transpose_f2h<<<dim3(16, 16, 1), tb>>>(wk, wt + 1 * sW, 512, 512);
    transpose_f2h<<<dim3(16, 16, 1), tb>>>(wv, wt + 2 * sW, 512, 512);
    transpose_f2h<<<dim3(16, 16, 1), tb>>>(wp, wt + 3 * sW, 512, 512);

    // QKV: [8192,512] = xn @ w^T (NT), + bias -> bf16
    dim3 gQKV(512 / BN, 8192 / BM, 1);
    gemm_bf16<<<gQKV, 256, GEMM_SMEM>>>(xn, wt + 0 * sW, q, bq, nullptr, 8192, 512, 512, 1.f, 0, 0, 0, 1);
    gemm_bf16<<<gQKV, 256, GEMM_SMEM>>>(xn, wt + 1 * sW, k, bk, nullptr, 8192, 512, 512, 1.f, 0, 0, 0, 1);
    gemm_bf16<<<gQKV, 256, GEMM_SMEM>>>(xn, wt + 2 * sW, v, bv, nullptr, 8192, 512, 512, 1.f, 0, 0, 0, 1);

    // S = scale * Q @ K^T per batch -> bf16 logits
    dim3 gS(4096 / BN, 4096 / BM, 2);
    gemm_bf16<<<gS, 256, GEMM_SMEM>>>(q, k, attn, nullptr, nullptr, 4096, 4096, 512, SCALE, sQ, sQ, sS, 1);

    // softmax rows (bf16 in/out, fp32 math)
    softmax4096_h<<<8192, 256>>>(attn);

    // V^T per batch: [512,4096] bf16
    transpose_h<<<dim3(16, 128, 2), tb>>>(v, vt, 4096, 512, sQ, sQ);

    // O = P @ V = P @ (V^T)^T  (NT) -> bf16
    dim3 gPV(512 / BN, 4096 / BM, 2);
    gemm_bf16<<<gPV, 256, GEMM_SMEM>>>(attn, vt, o, nullptr, nullptr, 4096, 512, 4096, 1.f, sS, sQ, sQ, 1);

    // out = O @ wp^T (NT) + bp + x  -> fp32
    dim3 gP(512 / BN, 8192 / BM, 1);
    gemm_bf16<<<gP, 256, GEMM_SMEM>>>(o, wt + 3 * sW, out, bp, x, 8192, 512, 512, 1.f, 0, 0, 0, 0);
}

// round 17
// speedup vs baseline: 6.3132x; 1.0031x over previous
#include <cuda_runtime.h>
#include <cuda_bf16.h>
#include <cstdint>
#include <cstddef>

// ---------------------------------------------------------------------------
// AttentionBlock via mma.sync bf16 m16n8k16 + ldmatrix operand feed.
//   GroupNorm(32) -> fused QKV -> softmax(QK^T/sqrt(C)) V -> proj + residual
//   B=2, N_tok=4096, C=512.  fp32 I/O, bf16 GEMM operands, fp32 accum.
// All GEMMs NT: D[m,n] = sum_k A[m,k]*B[n,k]; weights / V pre-transposed.
// ---------------------------------------------------------------------------

typedef __nv_bfloat16  bf16;
typedef __nv_bfloat162 bf162;

// ---------------- GEMM tile config ----------------
#define BM 128
#define BN 128
#define BKH 64                       // bf16 elements per K-chunk (4 mma k-steps of 16)
#define NST 3                        // cp.async pipeline stages
#define PITCH 72                     // padded row pitch in bf16 elems (144 B)
#define A_HALFS (BM * PITCH)         // 9216
#define STG_HALFS (2 * A_HALFS)      // 18432 bf16 per stage (A + B)
#define GEMM_SMEM (NST * STG_HALFS * 2)   // 110592 bytes -> 2 CTA/SM

// ---------------- scratch (allocation-free) ----------------
__device__ bf16  h_xn  [8192 * 512];
__device__ bf16  h_qkv [8192 * 1536];               // fused Q|K|V, row stride 1536
__device__ bf16  h_vt  [8192 * 512];                // V^T per batch: [512,4096]
__device__ bf16  h_o   [8192 * 512];
__device__ bf16  h_wt  [4 * 512 * 512];             // wq^T|wk^T|wv^T (=[1536,512]), wp^T
__device__ bf16  h_attn[(size_t)2 * 4096 * 4096];
__device__ float g_part1[1024];
__device__ float g_part2[1024];
__device__ float g_mean[64];
__device__ float g_rstd[64];
__device__ float g_bias[1536];

// ---------------- helpers ----------------
__device__ __forceinline__ uint32_t smem_u32(const void* p) {
    uint32_t a;
    asm("{ .reg .u64 t; cvta.to.shared.u64 t, %1; cvt.u32.u64 %0, t; }" : "=r"(a) : "l"(p));
    return a;
}
__device__ __forceinline__ void cpa16(uint32_t dst, const void* src) {
    asm volatile("cp.async.cg.shared.global [%0], [%1], 16;" :: "r"(dst), "l"(src));
}
#define LDSM_X4(r, addr) \
    asm volatile("ldmatrix.sync.aligned.m8n8.x4.shared.b16 {%0,%1,%2,%3}, [%4];" \
        : "=r"((r)[0]), "=r"((r)[1]), "=r"((r)[2]), "=r"((r)[3]) : "r"(addr))

// ---------------------------------------------------------------------------
// GroupNorm stats, two-stage.
// Stage 1: 1024 blocks = 64 (b,g) groups x 16 pixel-slices of 256 pixels.
// ---------------------------------------------------------------------------
__global__ void gn_stats1(const float* __restrict__ x) {
    int blk = blockIdx.x;                 // 0..1023
    int bg  = blk >> 4;                   // (b,g)
    int sl  = blk & 15;                   // pixel slice
    int b   = bg >> 5, g = bg & 31;
    const float* base = x + (size_t)b * 4096 * 512 + g * 16;
    const int t = threadIdx.x;            // 256
    const int cq = (t & 3) * 4;           // channel quad within group (0,4,8,12)
    const int pofs = t >> 2;              // 0..63

    float s = 0.f, ss = 0.f;
#pragma unroll
    for (int pp = 0; pp < 4; pp++) {
        int p = sl * 256 + pp * 64 + pofs;
        float4 v = *(const float4*)(base + (size_t)p * 512 + cq);
        s  += v.x + v.y + v.z + v.w;
        ss += v.x * v.x + v.y * v.y + v.z * v.z + v.w * v.w;
    }
    __shared__ float sh1[256], sh2[256];
    sh1[t] = s; sh2[t] = ss;
    __syncthreads();
    for (int st = 128; st > 0; st >>= 1) {
        if (t < st) { sh1[t] += sh1[t + st]; sh2[t] += sh2[t + st]; }
        __syncthreads();
    }
    if (t == 0) { g_part1[blk] = sh1[0]; g_part2[blk] = sh2[0]; }
}

// Stage 2: 64 threads, each reduces its group's 16 partials (deterministic).
__global__ void gn_stats2() {
    int bg = threadIdx.x;                 // 0..63
    float s = 0.f, ss = 0.f;
#pragma unroll
    for (int i = 0; i < 16; i++) { s += g_part1[bg * 16 + i]; ss += g_part2[bg * 16 + i]; }
    float m   = s  * (1.f / 65536.f);
    float var = ss * (1.f / 65536.f) - m * m;
    g_mean[bg] = m;
    g_rstd[bg] = rsqrtf(var + 1e-5f);
}

__global__ void gn_apply(const float* __restrict__ x,
                         const float* __restrict__ gamma,
                         const float* __restrict__ beta,
                         bf16* __restrict__ xn) {
    size_t e = ((size_t)blockIdx.x * blockDim.x + threadIdx.x) * 4;
    int c = (int)(e & 511);
    int b = (int)(e >> 21);
    int bg = b * 32 + (c >> 4);
    float m = g_mean[bg], r = g_rstd[bg];
    float4 xv = *(const float4*)(x + e);
    float o0 = (xv.x - m) * r * gamma[c + 0] + beta[c + 0];
    float o1 = (xv.y - m) * r * gamma[c + 1] + beta[c + 1];
    float o2 = (xv.z - m) * r * gamma[c + 2] + beta[c + 2];
    float o3 = (xv.w - m) * r * gamma[c + 3] + beta[c + 3];
    bf162 p0; p0.x = __float2bfloat16(o0); p0.y = __float2bfloat16(o1);
    bf162 p1; p1.x = __float2bfloat16(o2); p1.y = __float2bfloat16(o3);
    *(bf162*)(xn + e)     = p0;
    *(bf162*)(xn + e + 2) = p1;
}

// Bias concat: g_bias = [bq | bk | bv]
__global__ void concat_bias(const float* __restrict__ bq, const float* __restrict__ bk,
                            const float* __restrict__ bv) {
    int i = blockIdx.x * 256 + threadIdx.x;   // 0..1535
    float v = (i < 512) ? bq[i] : (i < 1024 ? bk[i - 512] : bv[i - 1024]);
    g_bias[i] = v;
}

// ---------------------------------------------------------------------------
// Transposes
// ---------------------------------------------------------------------------
__global__ void transpose_f2h(const float* __restrict__ in, bf16* __restrict__ out,
                              int R, int C) {
    __shared__ float t[32][33];
    int c0 = blockIdx.x * 32, r0 = blockIdx.y * 32;
    int tx = threadIdx.x, ty = threadIdx.y;
#pragma unroll
    for (int i = 0; i < 32; i += 8)
        t[ty + i][tx] = in[(size_t)(r0 + ty + i) * C + c0 + tx];
    __syncthreads();
#pragma unroll
    for (int i = 0; i < 32; i += 8)
        out[(size_t)(c0 + ty + i) * R + r0 + tx] = __float2bfloat16(t[tx][ty + i]);
}

// bf16 [R, ldIn-strided] -> bf16 [C, R] per batch (V^T); grid.x covers 512 cols
__global__ void transpose_h(const bf16* __restrict__ in, bf16* __restrict__ out,
                            int R, int ldIn, size_t sIn, size_t sOut) {
    in  += (size_t)blockIdx.z * sIn;
    out += (size_t)blockIdx.z * sOut;
    __shared__ bf16 t[32][34];
    int c0 = blockIdx.x * 32, r0 = blockIdx.y * 32;
    int tx = threadIdx.x, ty = threadIdx.y;
#pragma unroll
    for (int i = 0; i < 32; i += 8)
        t[ty + i][tx] = in[(size_t)(r0 + ty + i) * ldIn + c0 + tx];
    __syncthreads();
#pragma unroll
    for (int i = 0; i < 32; i += 8)
        out[(size_t)(c0 + ty + i) * R + r0 + tx] = t[tx][ty + i];
}

// ---------------------------------------------------------------------------
// bf16 mma.sync GEMM (NT): D = scale*(A @ B^T) [+ bias] [+ residual]
//   A row stride lda, B row stride ldb, D row stride ldc (elements).
//   CTA tile 128x128x64, 8 warps (2m x 4n), warp tile 64x32, mma m16n8k16.
//   ldmatrix.x4 operand feed; 3-stage cp.async pipeline; 256 threads.
// ---------------------------------------------------------------------------
__global__ void __launch_bounds__(256, 2)
gemm_bf16(const bf16* __restrict__ A, int lda, const bf16* __restrict__ B, int ldb,
          void* __restrict__ Cv, int ldc, const float* __restrict__ bias,
          const float* __restrict__ residual,
          int K, float scale, size_t sA, size_t sB, size_t sC, int outHalf) {
    extern __shared__ bf16 smh[];
    const uint32_t saddr = smem_u32(smh);
    const int tid = threadIdx.x;
    const int wid = tid >> 5, lid = tid & 31;
    const int gid = lid >> 2, tig = lid & 3;     // quad row / thread-in-group
    const int wm  = wid >> 2, wn  = wid & 3;     // warp grid 2x4

    const int row0 = blockIdx.y * BM;
    const int col0 = blockIdx.x * BN;
    const bf16* Ab = A + (size_t)blockIdx.z * sA + (size_t)row0 * lda;
    const bf16* Bb = B + (size_t)blockIdx.z * sB + (size_t)col0 * ldb;

    // ldmatrix per-lane source offsets (bytes, within stage)
    const int lAr = (lid & 7) + ((lid >> 3) & 1) * 8;
    const int lAc = (lid >> 4) * 8;
    const int lBr = (lid & 7) + (lid >> 4) * 8;
    const int lBc = ((lid >> 3) & 1) * 8;
    const uint32_t aOff = saddr + 2u * (uint32_t)((wm * 64 + lAr) * PITCH + lAc);
    const uint32_t bOff = saddr + 2u * (uint32_t)(A_HALFS + (wn * 32 + lBr) * PITCH + lBc);

    float acc[4][4][4];
#pragma unroll
    for (int i = 0; i < 4; i++)
#pragma unroll
        for (int j = 0; j < 4; j++)
#pragma unroll
            for (int r = 0; r < 4; r++) acc[i][j][r] = 0.f;

    const int nch = K / BKH;

    auto load_stage = [&](int s, int kt) {
        uint32_t dA = saddr + (uint32_t)(s * STG_HALFS) * 2u;
        uint32_t dB = dA + (uint32_t)A_HALFS * 2u;
        const bf16* Ak = Ab + kt * BKH;
        const bf16* Bk = Bb + kt * BKH;
#pragma unroll
        for (int i = 0; i < 4; i++) {            // A: 128 rows x 8 x 16B
            int idx = tid + 256 * i;
            int r = idx >> 3, e = idx & 7;
            cpa16(dA + (uint32_t)(r * PITCH + e * 8) * 2u, Ak + (size_t)r * lda + e * 8);
        }
#pragma unroll
        for (int i = 0; i < 4; i++) {            // B: 128 rows x 8 x 16B
            int idx = tid + 256 * i;
            int r = idx >> 3, e = idx & 7;
            cpa16(dB + (uint32_t)(r * PITCH + e * 8) * 2u, Bk + (size_t)r * ldb + e * 8);
        }
        asm volatile("cp.async.commit_group;" ::: "memory");
    };

    load_stage(0, 0);
    load_stage(1, 1);

    for (int kt = 0; kt < nch; kt++) {
        int s = kt % NST;
        if (kt == nch - 1) asm volatile("cp.async.wait_group 0;" ::: "memory");
        else               asm volatile("cp.async.wait_group 1;" ::: "memory");
        __syncthreads();
        if (kt + 2 < nch) load_stage((kt + 2) % NST, kt + 2);

        const uint32_t stB = (uint32_t)(s * STG_HALFS) * 2u;

#pragma unroll
        for (int ks = 0; ks < 4; ks++) {
            uint32_t a[4][4], b[2][4];
#pragma unroll
            for (int mt = 0; mt < 4; mt++)
                LDSM_X4(a[mt], aOff + stB + (uint32_t)(mt * 16 * PITCH + ks * 16) * 2u);
#pragma unroll
            for (int p = 0; p < 2; p++)
                LDSM_X4(b[p], bOff + stB + (uint32_t)(p * 16 * PITCH + ks * 16) * 2u);

#pragma unroll
            for (int mt = 0; mt < 4; mt++)
#pragma unroll
                for (int nt = 0; nt < 4; nt++)
                    asm volatile(
                        "mma.sync.aligned.m16n8k16.row.col.f32.bf16.bf16.f32 "
                        "{%0,%1,%2,%3}, {%4,%5,%6,%7}, {%8,%9}, {%0,%1,%2,%3};"
                        : "+f"(acc[mt][nt][0]), "+f"(acc[mt][nt][1]),
                          "+f"(acc[mt][nt][2]), "+f"(acc[mt][nt][3])
                        : "r"(a[mt][0]), "r"(a[mt][1]), "r"(a[mt][2]), "r"(a[mt][3]),
                          "r"(b[nt >> 1][(nt & 1) * 2]), "r"(b[nt >> 1][(nt & 1) * 2 + 1]));
        }
    }

    // ---- epilogue ----
    if (outHalf) {
        bf16* Ch = (bf16*)Cv + (size_t)blockIdx.z * sC;
#pragma unroll
        for (int mt = 0; mt < 4; mt++) {
            int r = row0 + wm * 64 + mt * 16 + gid;
#pragma unroll
            for (int nt = 0; nt < 4; nt++) {
                int c = col0 + wn * 32 + nt * 8 + 2 * tig;
#pragma unroll
                for (int h = 0; h < 2; h++) {
                    int rr = r + h * 8;
                    float v0 = acc[mt][nt][2 * h + 0] * scale;
                    float v1 = acc[mt][nt][2 * h + 1] * scale;
                    if (bias) { v0 += bias[c]; v1 += bias[c + 1]; }
                    bf162 hv; hv.x = __float2bfloat16(v0); hv.y = __float2bfloat16(v1);
                    *(bf162*)(Ch + (size_t)rr * ldc + c) = hv;
                }
            }
        }
    } else {
        float* Cf = (float*)Cv + (size_t)blockIdx.z * sC;
        const float* Rb = residual ? residual + (size_t)blockIdx.z * sC : nullptr;
#pragma unroll
        for (int mt = 0; mt < 4; mt++) {
            int r = row0 + wm * 64 + mt * 16 + gid;
#pragma unroll
            for (int nt = 0; nt < 4; nt++) {
                int c = col0 + wn * 32 + nt * 8 + 2 * tig;
#pragma unroll
                for (int h = 0; h < 2; h++) {
                    int rr = r + h * 8;
                    float v0 = acc[mt][nt][2 * h + 0] * scale;
                    float v1 = acc[mt][nt][2 * h + 1] * scale;
                    if (bias) { v0 += bias[c]; v1 += bias[c + 1]; }
                    if (Rb) {
                        float2 rv = *(const float2*)(Rb + (size_t)rr * ldc + c);
                        v0 += rv.x; v1 += rv.y;
                    }
                    *(float2*)(Cf + (size_t)rr * ldc + c) = make_float2(v0, v1);
                }
            }
        }
    }
}

// ---------------------------------------------------------------------------
// Row softmax over bf16 logits, length 4096, in-place. fp32 math.
// ---------------------------------------------------------------------------
__global__ void softmax4096_h(bf16* __restrict__ S) {
    uint32_t* p = (uint32_t*)(S + (size_t)blockIdx.x * 4096);
    const int t = threadIdx.x;
    __shared__ float sh[8];

    float v[16];
#pragma unroll
    for (int i = 0; i < 8; i++) {
        uint32_t u = p[t + i * 256];
        bf162 h2 = *reinterpret_cast<bf162*>(&u);
        v[2 * i]     = __bfloat162float(h2.x);
        v[2 * i + 1] = __bfloat162float(h2.y);
    }
    float mx = -1e30f;
#pragma unroll
    for (int i = 0; i < 16; i++) mx = fmaxf(mx, v[i]);
#pragma unroll
    for (int off = 16; off > 0; off >>= 1)
        mx = fmaxf(mx, __shfl_xor_sync(0xffffffffu, mx, off));
    if ((t & 31) == 0) sh[t >> 5] = mx;
    __syncthreads();
    {
        float m = sh[t & 7];
#pragma unroll
        for (int off = 4; off > 0; off >>= 1)
            m = fmaxf(m, __shfl_xor_sync(0xffffffffu, m, off));
        mx = m;
    }
    __syncthreads();

    float s = 0.f;
#pragma unroll
    for (int i = 0; i < 16; i++) {
        v[i] = __expf(v[i] - mx);
        s += v[i];
    }
#pragma unroll
    for (int off = 16; off > 0; off >>= 1)
        s += __shfl_xor_sync(0xffffffffu, s, off);
    if ((t & 31) == 0) sh[t >> 5] = s;
    __syncthreads();
    {
        float m = sh[t & 7];
#pragma unroll
        for (int off = 4; off > 0; off >>= 1)
            m += __shfl_xor_sync(0xffffffffu, m, off);
        s = m;
    }
    float inv = 1.f / s;
#pragma unroll
    for (int i = 0; i < 8; i++) {
        bf162 h2;
        h2.x = __float2bfloat16(v[2 * i] * inv);
        h2.y = __float2bfloat16(v[2 * i + 1] * inv);
        p[t + i * 256] = *reinterpret_cast<uint32_t*>(&h2);
    }
}

// ---------------------------------------------------------------------------
// Launch
// ---------------------------------------------------------------------------
extern "C" void kernel_launch(void* const* d_in, const int* in_sizes, int n_in,
                              void* d_out, int out_size) {
    (void)in_sizes; (void)n_in; (void)out_size;

    const float* x     = (const float*)d_in[0];
    const float* gamma = (const float*)d_in[1];
    const float* beta  = (const float*)d_in[2];
    const float* wq    = (const float*)d_in[3];
    const float* bq    = (const float*)d_in[4];
    const float* wk    = (const float*)d_in[5];
    const float* bk    = (const float*)d_in[6];
    const float* wv    = (const float*)d_in[7];
    const float* bv    = (const float*)d_in[8];
    const float* wp    = (const float*)d_in[9];
    const float* bp    = (const float*)d_in[10];
    float* out = (float*)d_out;

    bf16 *xn, *qkv, *vt, *o, *wt, *attn;
    float* bias;
    cudaGetSymbolAddress((void**)&xn,   h_xn);
    cudaGetSymbolAddress((void**)&qkv,  h_qkv);
    cudaGetSymbolAddress((void**)&vt,   h_vt);
    cudaGetSymbolAddress((void**)&o,    h_o);
    cudaGetSymbolAddress((void**)&wt,   h_wt);
    cudaGetSymbolAddress((void**)&attn, h_attn);
    cudaGetSymbolAddress((void**)&bias, g_bias);

    cudaFuncSetAttribute(gemm_bf16, cudaFuncAttributeMaxDynamicSharedMemorySize, GEMM_SMEM);

    const float SCALE = 0.04419417382415922f;   // 1/sqrt(512)
    const size_t sQKV = (size_t)4096 * 1536;    // per-batch stride of qkv views
    const size_t sQ   = (size_t)4096 * 512;
    const size_t sS   = (size_t)4096 * 4096;
    const size_t sW   = (size_t)512 * 512;

    // GroupNorm -> bf16 xn
    gn_stats1<<<1024, 256>>>(x);
    gn_stats2<<<1, 64>>>();
    gn_apply<<<4096, 256>>>(x, gamma, beta, xn);

    // Weight transposes (fp32 -> bf16); wt[0..1535] = [wq^T;wk^T;wv^T], +3*sW = wp^T
    dim3 tb(32, 8);
    transpose_f2h<<<dim3(16, 16, 1), tb>>>(wq, wt + 0 * sW, 512, 512);
    transpose_f2h<<<dim3(16, 16, 1), tb>>>(wk, wt + 1 * sW, 512, 512);
    transpose_f2h<<<dim3(16, 16, 1), tb>>>(wv, wt + 2 * sW, 512, 512);
    transpose_f2h<<<dim3(16, 16, 1), tb>>>(wp, wt + 3 * sW, 512, 512);
    concat_bias<<<6, 256>>>(bq, bk, bv);

    // Fused QKV: [8192,1536] = xn @ [wq|wk|wv]^T + bias
    dim3 gQKV(1536 / BN, 8192 / BM, 1);
    gemm_bf16<<<gQKV, 256, GEMM_SMEM>>>(xn, 512, wt, 512, qkv, 1536, bias, nullptr,
                                        512, 1.f, 0, 0, 0, 1);

    const bf16* q = qkv;
    const bf16* k = qkv + 512;
    const bf16* v = qkv + 1024;

    // S = scale * Q @ K^T per batch -> bf16 logits
    dim3 gS(4096 / BN, 4096 / BM, 2);
    gemm_bf16<<<gS, 256, GEMM_SMEM>>>(q, 1536, k, 1536, attn, 4096, nullptr, nullptr,
                                      512, SCALE, sQKV, sQKV, sS, 1);

    // softmax rows (bf16 in/out, fp32 math)
    softmax4096_h<<<8192, 256>>>(attn);

    // V^T per batch: [512,4096] bf16   (reads v view, row stride 1536)
    transpose_h<<<dim3(16, 128, 2), tb>>>(v, vt, 4096, 1536, sQKV, sQ);

    // O = P @ V = P @ (V^T)^T  (NT) -> bf16
    dim3 gPV(512 / BN, 4096 / BM, 2);
    gemm_bf16<<<gPV, 256, GEMM_SMEM>>>(attn, 4096, vt, 4096, o, 512, nullptr, nullptr,
                                       4096, 1.f, sS, sQ, sQ, 1);

    // out = O @ wp^T (NT) + bp + x  -> fp32
    dim3 gP(512 / BN, 8192 / BM, 1);
    gemm_bf16<<<gP, 256, GEMM_SMEM>>>(o, 512, wt + 3 * sW, 512, out, 512, bp, x,
                                      512, 1.f, 0, 0, 0, 0);
}